// round 1
// baseline (speedup 1.0000x reference)
#include <cuda_runtime.h>
#include <cuda_bf16.h>
#include <math.h>

// Problem constants (fixed by setup_inputs)
#define BB 4
#define QQ 10000
#define EE 256
#define NHH 8
#define DD 32
#define LL 4
#define NPP 8
#define S_TOTAL 19560

// spatial shapes: {92,160},{46,80},{23,40},{12,20}
__constant__ int c_HL[4] = {92, 46, 23, 12};
__constant__ int c_WL[4] = {160, 80, 40, 20};
__constant__ int c_ST[4] = {0, 14720, 18400, 19320};

// Scratch (no cudaMalloc allowed)
__device__ float g_v[BB * S_TOTAL * EE];      // projected value [B,S,NH,D]
__device__ float g_off[BB * QQ * 512];        // offsets [B,Q,NH,L,NP,2]
__device__ float g_attn[BB * QQ * 256];       // attn logits [B,Q,NH,L*NP]

// ---------------------------------------------------------------------------
// Classic 128x128x8 fp32 SGEMM with bias epilogue. N must be multiple of 128,
// K multiple of 8. M edge guarded.
// ---------------------------------------------------------------------------
__global__ __launch_bounds__(256) void sgemm_bias(
    const float* __restrict__ A, const float* __restrict__ Bm,
    const float* __restrict__ bias, float* __restrict__ C,
    int M, int N, int K)
{
    __shared__ float As[8][128];
    __shared__ float Bs[8][128];

    const int tid = threadIdx.x;
    const int bm = blockIdx.y * 128;
    const int bn = blockIdx.x * 128;
    const int tx = tid & 15;
    const int ty = tid >> 4;

    float acc[8][8];
#pragma unroll
    for (int i = 0; i < 8; i++)
#pragma unroll
        for (int j = 0; j < 8; j++) acc[i][j] = 0.f;

    const int arow = tid >> 1;           // 0..127
    const int acol = (tid & 1) * 4;      // 0 or 4
    const int brow = tid >> 5;           // 0..7
    const int bcol = (tid & 31) * 4;     // 0..124

    for (int kk = 0; kk < K; kk += 8) {
        float4 a4 = make_float4(0.f, 0.f, 0.f, 0.f);
        if (bm + arow < M)
            a4 = *reinterpret_cast<const float4*>(A + (size_t)(bm + arow) * K + kk + acol);
        As[acol + 0][arow] = a4.x;
        As[acol + 1][arow] = a4.y;
        As[acol + 2][arow] = a4.z;
        As[acol + 3][arow] = a4.w;

        float4 b4 = *reinterpret_cast<const float4*>(Bm + (size_t)(kk + brow) * N + bn + bcol);
        *reinterpret_cast<float4*>(&Bs[brow][bcol]) = b4;
        __syncthreads();

#pragma unroll
        for (int k = 0; k < 8; k++) {
            float ra[8], rb[8];
            *reinterpret_cast<float4*>(&ra[0]) = *reinterpret_cast<const float4*>(&As[k][ty * 8 + 0]);
            *reinterpret_cast<float4*>(&ra[4]) = *reinterpret_cast<const float4*>(&As[k][ty * 8 + 4]);
            *reinterpret_cast<float4*>(&rb[0]) = *reinterpret_cast<const float4*>(&Bs[k][tx * 8 + 0]);
            *reinterpret_cast<float4*>(&rb[4]) = *reinterpret_cast<const float4*>(&Bs[k][tx * 8 + 4]);
#pragma unroll
            for (int i = 0; i < 8; i++)
#pragma unroll
                for (int j = 0; j < 8; j++)
                    acc[i][j] = fmaf(ra[i], rb[j], acc[i][j]);
        }
        __syncthreads();
    }

#pragma unroll
    for (int i = 0; i < 8; i++) {
        int r = bm + ty * 8 + i;
        if (r < M) {
#pragma unroll
            for (int j = 0; j < 8; j += 4) {
                int c = bn + tx * 8 + j;
                float4 o;
                o.x = acc[i][j + 0] + bias[c + 0];
                o.y = acc[i][j + 1] + bias[c + 1];
                o.z = acc[i][j + 2] + bias[c + 2];
                o.w = acc[i][j + 3] + bias[c + 3];
                *reinterpret_cast<float4*>(C + (size_t)r * N + c) = o;
            }
        }
    }
}

// ---------------------------------------------------------------------------
// Fused softmax + bilinear sampling. One warp per (b,q,h); lane = channel d,
// and lane also carries per-point (l,p) metadata broadcast via shfl.
// ---------------------------------------------------------------------------
__global__ __launch_bounds__(256) void sample_kernel(
    const float* __restrict__ ref,   // [B,Q,4,2]
    float* __restrict__ out)         // [B,Q,256]
{
    const int warp_global = blockIdx.x * 8 + (threadIdx.x >> 5);
    const int lane = threadIdx.x & 31;
    if (warp_global >= BB * QQ * NHH) return;

    const int h = warp_global % NHH;
    const int bq = warp_global / NHH;     // b*Q + q
    const int b = bq / QQ;

    // ---- softmax over L*NP = 32 logits (one per lane) ----
    float logit = g_attn[(size_t)bq * 256 + h * 32 + lane];
    float m = logit;
#pragma unroll
    for (int o = 16; o; o >>= 1) m = fmaxf(m, __shfl_xor_sync(0xFFFFFFFFu, m, o));
    float e = __expf(logit - m);
    float s = e;
#pragma unroll
    for (int o = 16; o; o >>= 1) s += __shfl_xor_sync(0xFFFFFFFFu, s, o);
    const float aw = e / s;

    // ---- per-lane point metadata: lane = l*8 + p ----
    const int l = lane >> 3;
    const int p = lane & 7;
    const int z = p & 3;                  // NP//Z=2, Z=4 -> p = pp*4 + z
    const float offx = g_off[(size_t)bq * 512 + h * 64 + lane * 2 + 0];
    const float offy = g_off[(size_t)bq * 512 + h * 64 + lane * 2 + 1];
    const float rx = ref[((size_t)bq * 4 + z) * 2 + 0];
    const float ry = ref[((size_t)bq * 4 + z) * 2 + 1];
    // px = loc.x*W - 0.5 = (rx + offx/W)*W - 0.5 = rx*W + offx - 0.5
    const float px = rx * (float)c_WL[l] + offx - 0.5f;
    const float py = ry * (float)c_HL[l] + offy - 0.5f;

    float acc = 0.f;
    const float* __restrict__ vbase = g_v + ((size_t)b * S_TOTAL) * EE + h * DD + lane;

#pragma unroll 4
    for (int j = 0; j < 32; j++) {
        const float pxj = __shfl_sync(0xFFFFFFFFu, px, j);
        const float pyj = __shfl_sync(0xFFFFFFFFu, py, j);
        const float wj  = __shfl_sync(0xFFFFFFFFu, aw, j);
        const int lj = j >> 3;
        const int Hl = c_HL[lj];
        const int Wl = c_WL[lj];
        const int st = c_ST[lj];

        const float x0f = floorf(pxj);
        const float y0f = floorf(pyj);
        const int x0 = (int)x0f;
        const int y0 = (int)y0f;
        const float fx = pxj - x0f;
        const float fy = pyj - y0f;

        const bool xin0 = (x0 >= 0) & (x0 < Wl);
        const bool xin1 = (x0 + 1 >= 0) & (x0 + 1 < Wl);
        const bool yin0 = (y0 >= 0) & (y0 < Hl);
        const bool yin1 = (y0 + 1 >= 0) & (y0 + 1 < Hl);

        float v00 = 0.f, v01 = 0.f, v10 = 0.f, v11 = 0.f;
        const float* lvl = vbase + (size_t)st * EE;
        if (yin0) {
            const float* row = lvl + (size_t)y0 * Wl * EE;
            if (xin0) v00 = row[(size_t)x0 * EE];
            if (xin1) v01 = row[(size_t)(x0 + 1) * EE];
        }
        if (yin1) {
            const float* row = lvl + (size_t)(y0 + 1) * Wl * EE;
            if (xin0) v10 = row[(size_t)x0 * EE];
            if (xin1) v11 = row[(size_t)(x0 + 1) * EE];
        }
        const float top = v00 + fx * (v01 - v00);
        const float bot = v10 + fx * (v11 - v10);
        acc = fmaf(wj, top + fy * (bot - top), acc);
    }

    out[(size_t)bq * 256 + h * 32 + lane] = acc;
}

// ---------------------------------------------------------------------------
extern "C" void kernel_launch(void* const* d_in, const int* in_sizes, int n_in,
                              void* d_out, int out_size)
{
    const float* query = (const float*)d_in[0];   // [4,10000,256]
    const float* value = (const float*)d_in[1];   // [4,19560,256]
    const float* ref   = (const float*)d_in[2];   // [4,10000,4,2]
    const float* w_off = (const float*)d_in[3];   // [256,512]
    const float* b_off = (const float*)d_in[4];   // [512]
    const float* w_att = (const float*)d_in[5];   // [256,256]
    const float* b_att = (const float*)d_in[6];   // [256]
    const float* w_val = (const float*)d_in[7];   // [256,256]
    const float* b_val = (const float*)d_in[8];   // [256]
    float* out = (float*)d_out;

    static float* p_v = nullptr;
    static float* p_off = nullptr;
    static float* p_attn = nullptr;
    if (!p_v) {
        cudaGetSymbolAddress((void**)&p_v, g_v);
        cudaGetSymbolAddress((void**)&p_off, g_off);
        cudaGetSymbolAddress((void**)&p_attn, g_attn);
    }

    // 1) v = value @ w_val + b_val   : M=78240, N=256, K=256
    {
        dim3 grid(256 / 128, (BB * S_TOTAL + 127) / 128);
        sgemm_bias<<<grid, 256>>>(value, w_val, b_val, p_v, BB * S_TOTAL, 256, 256);
    }
    // 2) off = query @ w_off + b_off : M=40000, N=512, K=256
    {
        dim3 grid(512 / 128, (BB * QQ + 127) / 128);
        sgemm_bias<<<grid, 256>>>(query, w_off, b_off, p_off, BB * QQ, 512, 256);
    }
    // 3) attn logits = query @ w_attn + b_attn : M=40000, N=256, K=256
    {
        dim3 grid(256 / 128, (BB * QQ + 127) / 128);
        sgemm_bias<<<grid, 256>>>(query, w_att, b_att, p_attn, BB * QQ, 256, 256);
    }
    // 4) fused softmax + sampling
    {
        int warps = BB * QQ * NHH;           // 320000
        int blocks = (warps + 7) / 8;        // 40000
        sample_kernel<<<blocks, 256>>>(ref, out);
    }
}

// round 3
// speedup vs baseline: 1.3022x; 1.3022x over previous
#include <cuda_runtime.h>
#include <cuda_bf16.h>
#include <math.h>
#include <stdint.h>

#define BB 4
#define QQ 10000
#define EE 256
#define NHH 8
#define S_TOTAL 19560

__constant__ int c_HL[4] = {92, 46, 23, 12};
__constant__ int c_WL[4] = {160, 80, 40, 20};
__constant__ int c_ST[4] = {0, 14720, 18400, 19320};

// Scratch (no cudaMalloc allowed)
__device__ float g_v[BB * S_TOTAL * EE];      // projected value [B,S,NH,D]
__device__ float g_off[BB * QQ * 512];        // offsets [B,Q,NH,L,NP,2]
__device__ float g_attn[BB * QQ * 256];       // attn logits [B,Q,NH,L*NP]

// Packed f32x2 FMA (Blackwell family feature, plain compute_103 OK)
#define FMA_F32X2(d, a, b, c) \
    asm("fma.rn.f32x2 %0, %1, %2, %3;" : "=l"(d) : "l"(a), "l"(b), "l"(c))
#define PACK_F32X2(out, lo, hi) \
    asm("mov.b64 %0, {%1, %2};" : "=l"(out) : "f"(lo), "f"(hi))
#define UNPACK_F32X2(lo, hi, in) \
    asm("mov.b64 {%0, %1}, %2;" : "=f"(lo), "=f"(hi) : "l"(in))

// ---------------------------------------------------------------------------
// 128x128x8 fp32 SGEMM with bias epilogue, inner product via fma.rn.f32x2.
// N multiple of 128, K multiple of 8. M edge guarded.
// ---------------------------------------------------------------------------
__global__ __launch_bounds__(256) void sgemm_bias(
    const float* __restrict__ A, const float* __restrict__ Bm,
    const float* __restrict__ bias, float* __restrict__ C,
    int M, int N, int K)
{
    __shared__ float As[8][128];
    __shared__ float Bs[8][128];

    const int tid = threadIdx.x;
    const int bm = blockIdx.y * 128;
    const int bn = blockIdx.x * 128;
    const int tx = tid & 15;
    const int ty = tid >> 4;

    unsigned long long acc2[8][4];
#pragma unroll
    for (int i = 0; i < 8; i++)
#pragma unroll
        for (int j = 0; j < 4; j++) acc2[i][j] = 0ull;

    const int arow = tid >> 1;           // 0..127
    const int acol = (tid & 1) * 4;      // 0 or 4
    const int brow = tid >> 5;           // 0..7
    const int bcol = (tid & 31) * 4;     // 0..124

    for (int kk = 0; kk < K; kk += 8) {
        float4 a4 = make_float4(0.f, 0.f, 0.f, 0.f);
        if (bm + arow < M)
            a4 = *reinterpret_cast<const float4*>(A + (size_t)(bm + arow) * K + kk + acol);
        As[acol + 0][arow] = a4.x;
        As[acol + 1][arow] = a4.y;
        As[acol + 2][arow] = a4.z;
        As[acol + 3][arow] = a4.w;

        float4 b4 = *reinterpret_cast<const float4*>(Bm + (size_t)(kk + brow) * N + bn + bcol);
        *reinterpret_cast<float4*>(&Bs[brow][bcol]) = b4;
        __syncthreads();

#pragma unroll
        for (int k = 0; k < 8; k++) {
            float ra[8];
            *reinterpret_cast<float4*>(&ra[0]) = *reinterpret_cast<const float4*>(&As[k][ty * 8 + 0]);
            *reinterpret_cast<float4*>(&ra[4]) = *reinterpret_cast<const float4*>(&As[k][ty * 8 + 4]);
            // B pairs straight out of shared memory as u64 lanes
            ulonglong2 b01 = *reinterpret_cast<const ulonglong2*>(&Bs[k][tx * 8 + 0]);
            ulonglong2 b23 = *reinterpret_cast<const ulonglong2*>(&Bs[k][tx * 8 + 4]);
            unsigned long long rb2[4] = {b01.x, b01.y, b23.x, b23.y};
#pragma unroll
            for (int i = 0; i < 8; i++) {
                unsigned long long ra2;
                PACK_F32X2(ra2, ra[i], ra[i]);
#pragma unroll
                for (int j = 0; j < 4; j++)
                    FMA_F32X2(acc2[i][j], ra2, rb2[j], acc2[i][j]);
            }
        }
        __syncthreads();
    }

#pragma unroll
    for (int i = 0; i < 8; i++) {
        int r = bm + ty * 8 + i;
        if (r < M) {
#pragma unroll
            for (int j = 0; j < 2; j++) {
                int c = bn + tx * 8 + j * 4;
                float4 o;
                UNPACK_F32X2(o.x, o.y, acc2[i][2 * j + 0]);
                UNPACK_F32X2(o.z, o.w, acc2[i][2 * j + 1]);
                o.x += bias[c + 0];
                o.y += bias[c + 1];
                o.z += bias[c + 2];
                o.w += bias[c + 3];
                *reinterpret_cast<float4*>(C + (size_t)r * N + c) = o;
            }
        }
    }
}

// ---------------------------------------------------------------------------
// Fused softmax + bilinear sampling. One warp per (b,q,h).
// Phase 1: lane = point (l,p); precompute 4 clamped corner byte-offsets and
//          4 pre-multiplied (bilinear x attn) weights into smem.
// Phase 2: warp splits into 2 point-halves; each lane covers 2 channels
//          via float2 loads; final shfl-xor reduction across halves.
// ---------------------------------------------------------------------------
__global__ __launch_bounds__(256) void sample_kernel(
    const float* __restrict__ ref, float* __restrict__ out)
{
    __shared__ int4 sidx[8][32];
    __shared__ float4 swgt[8][32];

    const int w = threadIdx.x >> 5;
    const int lane = threadIdx.x & 31;
    const int warp_global = blockIdx.x * 8 + w;
    const int h = warp_global & 7;
    const int bq = warp_global >> 3;
    const int b = bq / QQ;

    // softmax over 32 logits (one per lane)
    float logit = g_attn[(size_t)bq * 256 + h * 32 + lane];
    float m = logit;
#pragma unroll
    for (int o = 16; o; o >>= 1) m = fmaxf(m, __shfl_xor_sync(0xFFFFFFFFu, m, o));
    float e = __expf(logit - m);
    float s = e;
#pragma unroll
    for (int o = 16; o; o >>= 1) s += __shfl_xor_sync(0xFFFFFFFFu, s, o);
    const float aw = e / s;

    // per-lane point: lane = l*8 + p
    const int l = lane >> 3;
    const int p = lane & 7;
    const int z = p & 3;
    const float2 off2 = *reinterpret_cast<const float2*>(g_off + (size_t)bq * 512 + h * 64 + lane * 2);
    const float2 r2 = *reinterpret_cast<const float2*>(ref + ((size_t)bq * 4 + z) * 2);
    const int W = c_WL[l], H = c_HL[l], st = c_ST[l];
    const float px = r2.x * (float)W + off2.x - 0.5f;
    const float py = r2.y * (float)H + off2.y - 0.5f;
    const float x0f = floorf(px), y0f = floorf(py);
    const int x0 = (int)x0f, y0 = (int)y0f;
    const float fx = px - x0f, fy = py - y0f;
    const float gx = 1.f - fx, gy = 1.f - fy;
    const bool xi0 = (x0 >= 0) && (x0 < W);
    const bool xi1 = (x0 >= -1) && (x0 < W - 1);
    const bool yi0 = (y0 >= 0) && (y0 < H);
    const bool yi1 = (y0 >= -1) && (y0 < H - 1);
    const int xc0 = min(max(x0, 0), W - 1);
    const int xc1 = min(max(x0 + 1, 0), W - 1);
    const int yc0 = min(max(y0, 0), H - 1);
    const int yc1 = min(max(y0 + 1, 0), H - 1);
    // byte offsets: (st + y*W + x) * 256 floats * 4B = << 10
    sidx[w][lane] = make_int4((st + yc0 * W + xc0) << 10, (st + yc0 * W + xc1) << 10,
                              (st + yc1 * W + xc0) << 10, (st + yc1 * W + xc1) << 10);
    swgt[w][lane] = make_float4(aw * gx * gy * (float)(xi0 && yi0),
                                aw * fx * gy * (float)(xi1 && yi0),
                                aw * gx * fy * (float)(xi0 && yi1),
                                aw * fx * fy * (float)(xi1 && yi1));
    __syncwarp();

    // halves process even/odd points; each lane handles 2 channels (float2)
    const int half = lane >> 4;
    const int ch2 = lane & 15;
    const char* vb = reinterpret_cast<const char*>(g_v + (size_t)b * S_TOTAL * 256 + h * 32) + ch2 * 8;
    float accx = 0.f, accy = 0.f;
#pragma unroll
    for (int j2 = 0; j2 < 16; j2++) {
        const int j = 2 * j2 + half;
        const int4 o = sidx[w][j];
        const float4 wt = swgt[w][j];
        const float2 v00 = *reinterpret_cast<const float2*>(vb + o.x);
        const float2 v01 = *reinterpret_cast<const float2*>(vb + o.y);
        const float2 v10 = *reinterpret_cast<const float2*>(vb + o.z);
        const float2 v11 = *reinterpret_cast<const float2*>(vb + o.w);
        accx = fmaf(wt.x, v00.x, fmaf(wt.y, v01.x, fmaf(wt.z, v10.x, fmaf(wt.w, v11.x, accx))));
        accy = fmaf(wt.x, v00.y, fmaf(wt.y, v01.y, fmaf(wt.z, v10.y, fmaf(wt.w, v11.y, accy))));
    }
    accx += __shfl_xor_sync(0xFFFFFFFFu, accx, 16);
    accy += __shfl_xor_sync(0xFFFFFFFFu, accy, 16);
    if (lane < 16) {
        reinterpret_cast<float2*>(out + (size_t)bq * 256 + h * 32)[ch2] = make_float2(accx, accy);
    }
}

// ---------------------------------------------------------------------------
extern "C" void kernel_launch(void* const* d_in, const int* in_sizes, int n_in,
                              void* d_out, int out_size)
{
    const float* query = (const float*)d_in[0];   // [4,10000,256]
    const float* value = (const float*)d_in[1];   // [4,19560,256]
    const float* ref   = (const float*)d_in[2];   // [4,10000,4,2]
    const float* w_off = (const float*)d_in[3];   // [256,512]
    const float* b_off = (const float*)d_in[4];   // [512]
    const float* w_att = (const float*)d_in[5];   // [256,256]
    const float* b_att = (const float*)d_in[6];   // [256]
    const float* w_val = (const float*)d_in[7];   // [256,256]
    const float* b_val = (const float*)d_in[8];   // [256]
    float* out = (float*)d_out;

    static float* p_v = nullptr;
    static float* p_off = nullptr;
    static float* p_attn = nullptr;
    if (!p_v) {
        cudaGetSymbolAddress((void**)&p_v, g_v);
        cudaGetSymbolAddress((void**)&p_off, g_off);
        cudaGetSymbolAddress((void**)&p_attn, g_attn);
    }

    // 1) v = value @ w_val + b_val   : M=78240, N=256, K=256
    {
        dim3 grid(256 / 128, (BB * S_TOTAL + 127) / 128);
        sgemm_bias<<<grid, 256>>>(value, w_val, b_val, p_v, BB * S_TOTAL, 256, 256);
    }
    // 2) off = query @ w_off + b_off : M=40000, N=512, K=256
    {
        dim3 grid(512 / 128, (BB * QQ + 127) / 128);
        sgemm_bias<<<grid, 256>>>(query, w_off, b_off, p_off, BB * QQ, 512, 256);
    }
    // 3) attn logits = query @ w_attn + b_attn : M=40000, N=256, K=256
    {
        dim3 grid(256 / 128, (BB * QQ + 127) / 128);
        sgemm_bias<<<grid, 256>>>(query, w_att, b_att, p_attn, BB * QQ, 256, 256);
    }
    // 4) fused softmax + sampling
    sample_kernel<<<BB * QQ * NHH / 8, 256>>>(ref, out);
}

// round 4
// speedup vs baseline: 2.3102x; 1.7741x over previous
#include <cuda_runtime.h>
#include <cuda_bf16.h>
#include <math.h>
#include <stdint.h>

#define BB 4
#define QQ 10000
#define EE 256
#define NHH 8
#define S_TOTAL 19560

__constant__ int c_HL[4] = {92, 46, 23, 12};
__constant__ int c_WL[4] = {160, 80, 40, 20};
__constant__ int c_ST[4] = {0, 14720, 18400, 19320};

// Scratch (no cudaMalloc allowed)
__device__ float g_v[BB * S_TOTAL * EE];
__device__ float g_off[BB * QQ * 512];
__device__ float g_attn[BB * QQ * 256];
__device__ __nv_bfloat16 g_vh[BB * S_TOTAL * EE];
__device__ __nv_bfloat16 g_vl[BB * S_TOTAL * EE];
__device__ __nv_bfloat16 g_qh[BB * QQ * EE];
__device__ __nv_bfloat16 g_ql[BB * QQ * EE];
__device__ __nv_bfloat16 g_wth[262144];   // transposed weights hi [n][k]
__device__ __nv_bfloat16 g_wtl[262144];   // transposed weights lo [n][k]

__device__ __forceinline__ uint32_t smem_u32(const void* p) {
    uint32_t a;
    asm("{ .reg .u64 t; cvta.to.shared.u64 t, %1; cvt.u32.u64 %0, t; }" : "=r"(a) : "l"(p));
    return a;
}

#define LDMATRIX_X4(r, addr) \
    asm volatile("ldmatrix.sync.aligned.m8n8.x4.shared.b16 {%0,%1,%2,%3}, [%4];" \
        : "=r"((r)[0]), "=r"((r)[1]), "=r"((r)[2]), "=r"((r)[3]) : "r"(addr))

#define MMA_BF16(d, a, b) \
    asm volatile("mma.sync.aligned.m16n8k16.row.col.f32.bf16.bf16.f32 " \
        "{%0,%1,%2,%3}, {%4,%5,%6,%7}, {%8,%9}, {%0,%1,%2,%3};" \
        : "+f"((d)[0]), "+f"((d)[1]), "+f"((d)[2]), "+f"((d)[3]) \
        : "r"((a)[0]), "r"((a)[1]), "r"((a)[2]), "r"((a)[3]), "r"((b)[0]), "r"((b)[1]))

// ------------------------- split / transpose kernels ------------------------
__global__ __launch_bounds__(256) void split_kernel(
    const float* __restrict__ in, __nv_bfloat16* __restrict__ hi,
    __nv_bfloat16* __restrict__ lo, int n4)
{
    int i = blockIdx.x * 256 + threadIdx.x;
    if (i >= n4) return;
    float4 v = reinterpret_cast<const float4*>(in)[i];
    __nv_bfloat16 h0 = __float2bfloat16(v.x);
    __nv_bfloat16 h1 = __float2bfloat16(v.y);
    __nv_bfloat16 h2 = __float2bfloat16(v.z);
    __nv_bfloat16 h3 = __float2bfloat16(v.w);
    __nv_bfloat16 l0 = __float2bfloat16(v.x - __bfloat162float(h0));
    __nv_bfloat16 l1 = __float2bfloat16(v.y - __bfloat162float(h1));
    __nv_bfloat16 l2 = __float2bfloat16(v.z - __bfloat162float(h2));
    __nv_bfloat16 l3 = __float2bfloat16(v.w - __bfloat162float(h3));
    __nv_bfloat162* ph = reinterpret_cast<__nv_bfloat162*>(hi);
    __nv_bfloat162* pl = reinterpret_cast<__nv_bfloat162*>(lo);
    ph[2 * i + 0] = __nv_bfloat162(h0, h1);
    ph[2 * i + 1] = __nv_bfloat162(h2, h3);
    pl[2 * i + 0] = __nv_bfloat162(l0, l1);
    pl[2 * i + 1] = __nv_bfloat162(l2, l3);
}

__global__ __launch_bounds__(256) void wsplit_kernel(
    const float* __restrict__ w, __nv_bfloat16* __restrict__ th,
    __nv_bfloat16* __restrict__ tl, int N)
{
    int idx = blockIdx.x * 256 + threadIdx.x;
    if (idx >= N * 256) return;
    int n = idx >> 8, k = idx & 255;
    float v = w[k * N + n];
    __nv_bfloat16 h = __float2bfloat16(v);
    th[idx] = h;
    tl[idx] = __float2bfloat16(v - __bfloat162float(h));
}

// ------------------------- mma.sync split-bf16 GEMM -------------------------
// C[M,N] = Ah@Bh^T + Ah@Bl^T + Al@Bh^T + bias. K=256 fixed. N mult of 128.
// A row-major [M][256] bf16; B row-major [N][256] bf16 (pre-transposed weight).
// Block 128x128, 8 warps as 2(M) x 4(N); warp tile 64x32.
// smem: 2 stages x 4 tiles (Ah,Al,Bh,Bl), each 128 rows x 48B (16 bf16 + pad).

#define STAGE_BYTES 24576
#define TILE_BYTES 6144

__device__ __forceinline__ void load_stage(
    uint32_t sbase, int stage,
    const char* Ah, const char* Al, const char* Bh, const char* Bl,
    int bm, int bn, int M, int c, int tid)
{
    const uint32_t dst0 = sbase + stage * STAGE_BYTES;
#pragma unroll
    for (int it = 0; it < 4; it++) {
        int i = tid + it * 256;
        int tile = i >> 8;
        int idx = i & 255;
        int row = idx >> 1;
        int half = (idx & 1) << 4;
        uint32_t dst = dst0 + tile * TILE_BYTES + row * 48 + half;
        const char* src;
        int ssize = 16;
        if (tile == 0) {
            src = Ah + (size_t)(bm + row) * 512 + c * 32 + half;
            if (bm + row >= M) ssize = 0;
        } else if (tile == 1) {
            src = Al + (size_t)(bm + row) * 512 + c * 32 + half;
            if (bm + row >= M) ssize = 0;
        } else if (tile == 2) {
            src = Bh + (size_t)(bn + row) * 512 + c * 32 + half;
        } else {
            src = Bl + (size_t)(bn + row) * 512 + c * 32 + half;
        }
        asm volatile("cp.async.ca.shared.global [%0], [%1], 16, %2;"
                     :: "r"(dst), "l"(src), "r"(ssize) : "memory");
    }
}

__global__ __launch_bounds__(256) void gemm_mma(
    const __nv_bfloat16* __restrict__ Ah_g, const __nv_bfloat16* __restrict__ Al_g,
    const __nv_bfloat16* __restrict__ Bh_g, const __nv_bfloat16* __restrict__ Bl_g,
    const float* __restrict__ bias, float* __restrict__ C, int M, int N)
{
    extern __shared__ char smem[];
    const uint32_t sbase = smem_u32(smem);
    const int tid = threadIdx.x;
    const int wid = tid >> 5, lane = tid & 31;
    const int warp_m = wid >> 2, warp_n = wid & 3;
    const int bm = blockIdx.y * 128, bn = blockIdx.x * 128;

    const char* Ahc = reinterpret_cast<const char*>(Ah_g);
    const char* Alc = reinterpret_cast<const char*>(Al_g);
    const char* Bhc = reinterpret_cast<const char*>(Bh_g);
    const char* Blc = reinterpret_cast<const char*>(Bl_g);

    float acc[4][4][4];
#pragma unroll
    for (int mt = 0; mt < 4; mt++)
#pragma unroll
        for (int nt = 0; nt < 4; nt++)
#pragma unroll
            for (int r = 0; r < 4; r++) acc[mt][nt][r] = 0.f;

    load_stage(sbase, 0, Ahc, Alc, Bhc, Blc, bm, bn, M, 0, tid);
    asm volatile("cp.async.commit_group;" ::: "memory");
    load_stage(sbase, 1, Ahc, Alc, Bhc, Blc, bm, bn, M, 1, tid);
    asm volatile("cp.async.commit_group;" ::: "memory");

    // ldmatrix lane addressing (within a 128-row tile, 48B row stride)
    const uint32_t a_row = warp_m * 64 + (lane & 15);
    const uint32_t a_off = (uint32_t)((lane >> 4) << 4);
    const uint32_t b_row = warp_n * 32 + (lane & 7) + ((lane >> 4) << 3);
    const uint32_t b_off = (uint32_t)(((lane >> 3) & 1) << 4);

#pragma unroll 1
    for (int c = 0; c < 16; c++) {
        asm volatile("cp.async.wait_group 1;" ::: "memory");
        __syncthreads();
        const uint32_t st = sbase + (c & 1) * STAGE_BYTES;

        uint32_t ah[4][4], al[4][4], bh[4][2], bl[4][2];
#pragma unroll
        for (int mt = 0; mt < 4; mt++) {
            uint32_t addr = st + (a_row + mt * 16) * 48 + a_off;
            LDMATRIX_X4(ah[mt], addr);
            LDMATRIX_X4(al[mt], addr + TILE_BYTES);
        }
#pragma unroll
        for (int g = 0; g < 2; g++) {
            uint32_t addr = st + 2 * TILE_BYTES + (b_row + g * 16) * 48 + b_off;
            uint32_t rh[4], rl[4];
            LDMATRIX_X4(rh, addr);
            LDMATRIX_X4(rl, addr + TILE_BYTES);
            bh[2 * g][0] = rh[0]; bh[2 * g][1] = rh[1];
            bh[2 * g + 1][0] = rh[2]; bh[2 * g + 1][1] = rh[3];
            bl[2 * g][0] = rl[0]; bl[2 * g][1] = rl[1];
            bl[2 * g + 1][0] = rl[2]; bl[2 * g + 1][1] = rl[3];
        }
        __syncthreads();

        if (c + 2 < 16)
            load_stage(sbase, c & 1, Ahc, Alc, Bhc, Blc, bm, bn, M, c + 2, tid);
        asm volatile("cp.async.commit_group;" ::: "memory");

#pragma unroll
        for (int mt = 0; mt < 4; mt++)
#pragma unroll
            for (int nt = 0; nt < 4; nt++) {
                MMA_BF16(acc[mt][nt], ah[mt], bh[nt]);
                MMA_BF16(acc[mt][nt], ah[mt], bl[nt]);
                MMA_BF16(acc[mt][nt], al[mt], bh[nt]);
            }
    }

    // epilogue: direct register -> global, bias added
    const int q = lane >> 2, t = lane & 3;
#pragma unroll
    for (int mt = 0; mt < 4; mt++) {
        int m0 = bm + warp_m * 64 + mt * 16 + q;
#pragma unroll
        for (int nt = 0; nt < 4; nt++) {
            int n = bn + warp_n * 32 + nt * 8 + 2 * t;
            float b0 = bias[n], b1 = bias[n + 1];
            if (m0 < M)
                *reinterpret_cast<float2*>(C + (size_t)m0 * N + n) =
                    make_float2(acc[mt][nt][0] + b0, acc[mt][nt][1] + b1);
            if (m0 + 8 < M)
                *reinterpret_cast<float2*>(C + (size_t)(m0 + 8) * N + n) =
                    make_float2(acc[mt][nt][2] + b0, acc[mt][nt][3] + b1);
        }
    }
}

// ------------------------- fused softmax + sampling -------------------------
__global__ __launch_bounds__(256) void sample_kernel(
    const float* __restrict__ ref, float* __restrict__ out)
{
    __shared__ int4 sidx[8][32];
    __shared__ float4 swgt[8][32];

    const int w = threadIdx.x >> 5;
    const int lane = threadIdx.x & 31;
    const int warp_global = blockIdx.x * 8 + w;
    const int h = warp_global & 7;
    const int bq = warp_global >> 3;
    const int b = bq / QQ;

    float logit = g_attn[(size_t)bq * 256 + h * 32 + lane];
    float m = logit;
#pragma unroll
    for (int o = 16; o; o >>= 1) m = fmaxf(m, __shfl_xor_sync(0xFFFFFFFFu, m, o));
    float e = __expf(logit - m);
    float s = e;
#pragma unroll
    for (int o = 16; o; o >>= 1) s += __shfl_xor_sync(0xFFFFFFFFu, s, o);
    const float aw = e / s;

    const int l = lane >> 3;
    const int p = lane & 7;
    const int z = p & 3;
    const float2 off2 = *reinterpret_cast<const float2*>(g_off + (size_t)bq * 512 + h * 64 + lane * 2);
    const float2 r2 = *reinterpret_cast<const float2*>(ref + ((size_t)bq * 4 + z) * 2);
    const int W = c_WL[l], H = c_HL[l], st = c_ST[l];
    const float px = r2.x * (float)W + off2.x - 0.5f;
    const float py = r2.y * (float)H + off2.y - 0.5f;
    const float x0f = floorf(px), y0f = floorf(py);
    const int x0 = (int)x0f, y0 = (int)y0f;
    const float fx = px - x0f, fy = py - y0f;
    const float gx = 1.f - fx, gy = 1.f - fy;
    const bool xi0 = (x0 >= 0) && (x0 < W);
    const bool xi1 = (x0 >= -1) && (x0 < W - 1);
    const bool yi0 = (y0 >= 0) && (y0 < H);
    const bool yi1 = (y0 >= -1) && (y0 < H - 1);
    const int xc0 = min(max(x0, 0), W - 1);
    const int xc1 = min(max(x0 + 1, 0), W - 1);
    const int yc0 = min(max(y0, 0), H - 1);
    const int yc1 = min(max(y0 + 1, 0), H - 1);
    sidx[w][lane] = make_int4((st + yc0 * W + xc0) << 10, (st + yc0 * W + xc1) << 10,
                              (st + yc1 * W + xc0) << 10, (st + yc1 * W + xc1) << 10);
    swgt[w][lane] = make_float4(aw * gx * gy * (float)(xi0 && yi0),
                                aw * fx * gy * (float)(xi1 && yi0),
                                aw * gx * fy * (float)(xi0 && yi1),
                                aw * fx * fy * (float)(xi1 && yi1));
    __syncwarp();

    const int half = lane >> 4;
    const int ch2 = lane & 15;
    const char* vb = reinterpret_cast<const char*>(g_v + (size_t)b * S_TOTAL * 256 + h * 32) + ch2 * 8;
    float accx = 0.f, accy = 0.f;
#pragma unroll
    for (int j2 = 0; j2 < 16; j2++) {
        const int j = 2 * j2 + half;
        const int4 o = sidx[w][j];
        const float4 wt = swgt[w][j];
        const float2 v00 = *reinterpret_cast<const float2*>(vb + o.x);
        const float2 v01 = *reinterpret_cast<const float2*>(vb + o.y);
        const float2 v10 = *reinterpret_cast<const float2*>(vb + o.z);
        const float2 v11 = *reinterpret_cast<const float2*>(vb + o.w);
        accx = fmaf(wt.x, v00.x, fmaf(wt.y, v01.x, fmaf(wt.z, v10.x, fmaf(wt.w, v11.x, accx))));
        accy = fmaf(wt.x, v00.y, fmaf(wt.y, v01.y, fmaf(wt.z, v10.y, fmaf(wt.w, v11.y, accy))));
    }
    accx += __shfl_xor_sync(0xFFFFFFFFu, accx, 16);
    accy += __shfl_xor_sync(0xFFFFFFFFu, accy, 16);
    if (lane < 16) {
        reinterpret_cast<float2*>(out + (size_t)bq * 256 + h * 32)[ch2] = make_float2(accx, accy);
    }
}

// ---------------------------------------------------------------------------
extern "C" void kernel_launch(void* const* d_in, const int* in_sizes, int n_in,
                              void* d_out, int out_size)
{
    const float* query = (const float*)d_in[0];
    const float* value = (const float*)d_in[1];
    const float* ref   = (const float*)d_in[2];
    const float* w_off = (const float*)d_in[3];
    const float* b_off = (const float*)d_in[4];
    const float* w_att = (const float*)d_in[5];
    const float* b_att = (const float*)d_in[6];
    const float* w_val = (const float*)d_in[7];
    const float* b_val = (const float*)d_in[8];
    float* out = (float*)d_out;

    static float *p_v = nullptr, *p_off = nullptr, *p_attn = nullptr;
    static __nv_bfloat16 *p_vh, *p_vl, *p_qh, *p_ql, *p_wth, *p_wtl;
    if (!p_v) {
        cudaGetSymbolAddress((void**)&p_v, g_v);
        cudaGetSymbolAddress((void**)&p_off, g_off);
        cudaGetSymbolAddress((void**)&p_attn, g_attn);
        cudaGetSymbolAddress((void**)&p_vh, g_vh);
        cudaGetSymbolAddress((void**)&p_vl, g_vl);
        cudaGetSymbolAddress((void**)&p_qh, g_qh);
        cudaGetSymbolAddress((void**)&p_ql, g_ql);
        cudaGetSymbolAddress((void**)&p_wth, g_wth);
        cudaGetSymbolAddress((void**)&p_wtl, g_wtl);
        cudaFuncSetAttribute(gemm_mma, cudaFuncAttributeMaxDynamicSharedMemorySize, 2 * STAGE_BYTES);
    }

    const int nv4 = BB * S_TOTAL * EE / 4;
    const int nq4 = BB * QQ * EE / 4;
    split_kernel<<<(nv4 + 255) / 256, 256>>>(value, p_vh, p_vl, nv4);
    split_kernel<<<(nq4 + 255) / 256, 256>>>(query, p_qh, p_ql, nq4);
    wsplit_kernel<<<(256 * 256 + 255) / 256, 256>>>(w_val, p_wth, p_wtl, 256);
    wsplit_kernel<<<(512 * 256 + 255) / 256, 256>>>(w_off, p_wth + 65536, p_wtl + 65536, 512);
    wsplit_kernel<<<(256 * 256 + 255) / 256, 256>>>(w_att, p_wth + 196608, p_wtl + 196608, 256);

    {
        dim3 grid(2, (BB * S_TOTAL + 127) / 128);
        gemm_mma<<<grid, 256, 2 * STAGE_BYTES>>>(p_vh, p_vl, p_wth, p_wtl, b_val, p_v, BB * S_TOTAL, 256);
    }
    {
        dim3 grid(4, (BB * QQ + 127) / 128);
        gemm_mma<<<grid, 256, 2 * STAGE_BYTES>>>(p_qh, p_ql, p_wth + 65536, p_wtl + 65536, b_off, p_off, BB * QQ, 512);
    }
    {
        dim3 grid(2, (BB * QQ + 127) / 128);
        gemm_mma<<<grid, 256, 2 * STAGE_BYTES>>>(p_qh, p_ql, p_wth + 196608, p_wtl + 196608, b_att, p_attn, BB * QQ, 256);
    }
    sample_kernel<<<BB * QQ * NHH / 8, 256>>>(ref, out);
}

// round 5
// speedup vs baseline: 2.7760x; 1.2016x over previous
#include <cuda_runtime.h>
#include <cuda_bf16.h>
#include <cuda_fp16.h>
#include <math.h>
#include <stdint.h>

#define BB 4
#define QQ 10000
#define EE 256
#define NHH 8
#define S_TOTAL 19560

__constant__ int c_HL[4] = {92, 46, 23, 12};
__constant__ int c_WL[4] = {160, 80, 40, 20};
__constant__ int c_ST[4] = {0, 14720, 18400, 19320};

// Scratch (no cudaMalloc allowed)
__device__ __half g_vf16[BB * NHH * S_TOTAL * 32];  // value proj, [B,NH,S,D] fp16
__device__ float g_off[BB * QQ * 512];
__device__ float g_attn[BB * QQ * 256];
__device__ __nv_bfloat16 g_vh[BB * S_TOTAL * EE];
__device__ __nv_bfloat16 g_vl[BB * S_TOTAL * EE];
__device__ __nv_bfloat16 g_qh[BB * QQ * EE];
__device__ __nv_bfloat16 g_ql[BB * QQ * EE];
__device__ __nv_bfloat16 g_wth[262144];
__device__ __nv_bfloat16 g_wtl[262144];

__device__ __forceinline__ uint32_t smem_u32(const void* p) {
    uint32_t a;
    asm("{ .reg .u64 t; cvta.to.shared.u64 t, %1; cvt.u32.u64 %0, t; }" : "=r"(a) : "l"(p));
    return a;
}

#define LDMATRIX_X4(r, addr) \
    asm volatile("ldmatrix.sync.aligned.m8n8.x4.shared.b16 {%0,%1,%2,%3}, [%4];" \
        : "=r"((r)[0]), "=r"((r)[1]), "=r"((r)[2]), "=r"((r)[3]) : "r"(addr))

#define MMA_BF16(d, a, b) \
    asm volatile("mma.sync.aligned.m16n8k16.row.col.f32.bf16.bf16.f32 " \
        "{%0,%1,%2,%3}, {%4,%5,%6,%7}, {%8,%9}, {%0,%1,%2,%3};" \
        : "+f"((d)[0]), "+f"((d)[1]), "+f"((d)[2]), "+f"((d)[3]) \
        : "r"((a)[0]), "r"((a)[1]), "r"((a)[2]), "r"((a)[3]), "r"((b)[0]), "r"((b)[1]))

// ------------------------- split / transpose kernels ------------------------
__global__ __launch_bounds__(256) void split_kernel(
    const float* __restrict__ in, __nv_bfloat16* __restrict__ hi,
    __nv_bfloat16* __restrict__ lo, int n4)
{
    int i = blockIdx.x * 256 + threadIdx.x;
    if (i >= n4) return;
    float4 v = reinterpret_cast<const float4*>(in)[i];
    __nv_bfloat16 h0 = __float2bfloat16(v.x);
    __nv_bfloat16 h1 = __float2bfloat16(v.y);
    __nv_bfloat16 h2 = __float2bfloat16(v.z);
    __nv_bfloat16 h3 = __float2bfloat16(v.w);
    __nv_bfloat16 l0 = __float2bfloat16(v.x - __bfloat162float(h0));
    __nv_bfloat16 l1 = __float2bfloat16(v.y - __bfloat162float(h1));
    __nv_bfloat16 l2 = __float2bfloat16(v.z - __bfloat162float(h2));
    __nv_bfloat16 l3 = __float2bfloat16(v.w - __bfloat162float(h3));
    __nv_bfloat162* ph = reinterpret_cast<__nv_bfloat162*>(hi);
    __nv_bfloat162* pl = reinterpret_cast<__nv_bfloat162*>(lo);
    ph[2 * i + 0] = __nv_bfloat162(h0, h1);
    ph[2 * i + 1] = __nv_bfloat162(h2, h3);
    pl[2 * i + 0] = __nv_bfloat162(l0, l1);
    pl[2 * i + 1] = __nv_bfloat162(l2, l3);
}

__global__ __launch_bounds__(256) void wsplit_kernel(
    const float* __restrict__ w, __nv_bfloat16* __restrict__ th,
    __nv_bfloat16* __restrict__ tl, int N)
{
    int idx = blockIdx.x * 256 + threadIdx.x;
    if (idx >= N * 256) return;
    int n = idx >> 8, k = idx & 255;
    float v = w[k * N + n];
    __nv_bfloat16 h = __float2bfloat16(v);
    th[idx] = h;
    tl[idx] = __float2bfloat16(v - __bfloat162float(h));
}

// ------------------------- mma.sync split-bf16 GEMM -------------------------
#define STAGE_BYTES 24576
#define TILE_BYTES 6144

__device__ __forceinline__ int bdiv_s(int m) {
    return (m >= 2 * S_TOTAL) ? (m >= 3 * S_TOTAL ? 3 : 2) : (m >= S_TOTAL ? 1 : 0);
}

__device__ __forceinline__ void load_stage(
    uint32_t sbase, int stage,
    const char* Ah, const char* Al, const char* Bh, const char* Bl,
    int bm, int bn, int M, int c, int tid)
{
    const uint32_t dst0 = sbase + stage * STAGE_BYTES;
#pragma unroll
    for (int it = 0; it < 4; it++) {
        int i = tid + it * 256;
        int tile = i >> 8;
        int idx = i & 255;
        int row = idx >> 1;
        int half = (idx & 1) << 4;
        uint32_t dst = dst0 + tile * TILE_BYTES + row * 48 + half;
        const char* src;
        int ssize = 16;
        if (tile == 0) {
            src = Ah + (size_t)(bm + row) * 512 + c * 32 + half;
            if (bm + row >= M) ssize = 0;
        } else if (tile == 1) {
            src = Al + (size_t)(bm + row) * 512 + c * 32 + half;
            if (bm + row >= M) ssize = 0;
        } else if (tile == 2) {
            src = Bh + (size_t)(bn + row) * 512 + c * 32 + half;
        } else {
            src = Bl + (size_t)(bn + row) * 512 + c * 32 + half;
        }
        asm volatile("cp.async.ca.shared.global [%0], [%1], 16, %2;"
                     :: "r"(dst), "l"(src), "r"(ssize) : "memory");
    }
}

// mode 0: C_f32[m][n] = acc + bias (row-major MxN)
// mode 1: value path — write fp16 to g_vf16 in [B,NH,S,D] layout
__global__ __launch_bounds__(256) void gemm_mma(
    const __nv_bfloat16* __restrict__ Ah_g, const __nv_bfloat16* __restrict__ Al_g,
    const __nv_bfloat16* __restrict__ Bh_g, const __nv_bfloat16* __restrict__ Bl_g,
    const float* __restrict__ bias, float* __restrict__ C, int M, int N, int mode)
{
    extern __shared__ char smem[];
    const uint32_t sbase = smem_u32(smem);
    const int tid = threadIdx.x;
    const int wid = tid >> 5, lane = tid & 31;
    const int warp_m = wid >> 2, warp_n = wid & 3;
    const int bm = blockIdx.y * 128, bn = blockIdx.x * 128;

    const char* Ahc = reinterpret_cast<const char*>(Ah_g);
    const char* Alc = reinterpret_cast<const char*>(Al_g);
    const char* Bhc = reinterpret_cast<const char*>(Bh_g);
    const char* Blc = reinterpret_cast<const char*>(Bl_g);

    float acc[4][4][4];
#pragma unroll
    for (int mt = 0; mt < 4; mt++)
#pragma unroll
        for (int nt = 0; nt < 4; nt++)
#pragma unroll
            for (int r = 0; r < 4; r++) acc[mt][nt][r] = 0.f;

    load_stage(sbase, 0, Ahc, Alc, Bhc, Blc, bm, bn, M, 0, tid);
    asm volatile("cp.async.commit_group;" ::: "memory");
    load_stage(sbase, 1, Ahc, Alc, Bhc, Blc, bm, bn, M, 1, tid);
    asm volatile("cp.async.commit_group;" ::: "memory");

    const uint32_t a_row = warp_m * 64 + (lane & 15);
    const uint32_t a_off = (uint32_t)((lane >> 4) << 4);
    const uint32_t b_row = warp_n * 32 + (lane & 7) + ((lane >> 4) << 3);
    const uint32_t b_off = (uint32_t)(((lane >> 3) & 1) << 4);

#pragma unroll 1
    for (int c = 0; c < 16; c++) {
        asm volatile("cp.async.wait_group 1;" ::: "memory");
        __syncthreads();
        const uint32_t st = sbase + (c & 1) * STAGE_BYTES;

        uint32_t ah[4][4], al[4][4], bh[4][2], bl[4][2];
#pragma unroll
        for (int mt = 0; mt < 4; mt++) {
            uint32_t addr = st + (a_row + mt * 16) * 48 + a_off;
            LDMATRIX_X4(ah[mt], addr);
            LDMATRIX_X4(al[mt], addr + TILE_BYTES);
        }
#pragma unroll
        for (int g = 0; g < 2; g++) {
            uint32_t addr = st + 2 * TILE_BYTES + (b_row + g * 16) * 48 + b_off;
            uint32_t rh[4], rl[4];
            LDMATRIX_X4(rh, addr);
            LDMATRIX_X4(rl, addr + TILE_BYTES);
            bh[2 * g][0] = rh[0]; bh[2 * g][1] = rh[1];
            bh[2 * g + 1][0] = rh[2]; bh[2 * g + 1][1] = rh[3];
            bl[2 * g][0] = rl[0]; bl[2 * g][1] = rl[1];
            bl[2 * g + 1][0] = rl[2]; bl[2 * g + 1][1] = rl[3];
        }
        __syncthreads();

        if (c + 2 < 16)
            load_stage(sbase, c & 1, Ahc, Alc, Bhc, Blc, bm, bn, M, c + 2, tid);
        asm volatile("cp.async.commit_group;" ::: "memory");

#pragma unroll
        for (int mt = 0; mt < 4; mt++)
#pragma unroll
            for (int nt = 0; nt < 4; nt++) {
                MMA_BF16(acc[mt][nt], ah[mt], bh[nt]);
                MMA_BF16(acc[mt][nt], ah[mt], bl[nt]);
                MMA_BF16(acc[mt][nt], al[mt], bh[nt]);
            }
    }

    const int q = lane >> 2, t = lane & 3;
    if (mode == 0) {
#pragma unroll
        for (int mt = 0; mt < 4; mt++) {
            int m0 = bm + warp_m * 64 + mt * 16 + q;
#pragma unroll
            for (int nt = 0; nt < 4; nt++) {
                int n = bn + warp_n * 32 + nt * 8 + 2 * t;
                float b0 = bias[n], b1 = bias[n + 1];
                if (m0 < M)
                    *reinterpret_cast<float2*>(C + (size_t)m0 * N + n) =
                        make_float2(acc[mt][nt][0] + b0, acc[mt][nt][1] + b1);
                if (m0 + 8 < M)
                    *reinterpret_cast<float2*>(C + (size_t)(m0 + 8) * N + n) =
                        make_float2(acc[mt][nt][2] + b0, acc[mt][nt][3] + b1);
            }
        }
    } else {
        // value path: m -> (b, s); n -> (h, d); dst = ((b*8+h)*S + s)*32 + d, fp16
        __half2* vf = reinterpret_cast<__half2*>(g_vf16);
#pragma unroll
        for (int mt = 0; mt < 4; mt++) {
            int m0 = bm + warp_m * 64 + mt * 16 + q;
#pragma unroll
            for (int nt = 0; nt < 4; nt++) {
                int n = bn + warp_n * 32 + nt * 8 + 2 * t;
                int h = n >> 5, d = n & 31;
                float b0 = bias[n], b1 = bias[n + 1];
#pragma unroll
                for (int rr = 0; rr < 2; rr++) {
                    int m = m0 + rr * 8;
                    if (m < M) {
                        int bb = bdiv_s(m);
                        int s = m - bb * S_TOTAL;
                        size_t idx = ((size_t)((bb * 8 + h)) * S_TOTAL + s) * 16 + (d >> 1);
                        vf[idx] = __floats2half2_rn(acc[mt][nt][2 * rr] + b0,
                                                    acc[mt][nt][2 * rr + 1] + b1);
                    }
                }
            }
        }
    }
}

// ------------------------- fused softmax + sampling -------------------------
// Phase 1: lane = point. Compute, per pixel p in {x0, x1}:
//   {addr_top, addr_bot, w_top, w_bot} (abs byte offsets into g_vf16, weights
//   pre-multiplied by attn & validity). 2 x 16B smem entries per point.
// Phase 2: 16 iters; lane = (half(point parity), p(pixel), c4(4 channels)).
//   One LDS.128 + two LDG.64(half4) + 8 FFMA per iter.
__global__ __launch_bounds__(256) void sample_kernel(
    const float* __restrict__ ref, float* __restrict__ out)
{
    __shared__ uint4 sMeta[8][64];

    const int w = threadIdx.x >> 5;
    const int lane = threadIdx.x & 31;
    const int warp_global = blockIdx.x * 8 + w;
    const int h = warp_global & 7;
    const int bq = warp_global >> 3;
    const int b = bq / QQ;

    // softmax over 32 logits
    float logit = g_attn[(size_t)bq * 256 + h * 32 + lane];
    float m = logit;
#pragma unroll
    for (int o = 16; o; o >>= 1) m = fmaxf(m, __shfl_xor_sync(0xFFFFFFFFu, m, o));
    float e = __expf(logit - m);
    float s = e;
#pragma unroll
    for (int o = 16; o; o >>= 1) s += __shfl_xor_sync(0xFFFFFFFFu, s, o);
    const float aw = e / s;

    const int l = lane >> 3;
    const int p = lane & 7;
    const int z = p & 3;
    const float2 off2 = *reinterpret_cast<const float2*>(g_off + (size_t)bq * 512 + h * 64 + lane * 2);
    const float2 r2 = *reinterpret_cast<const float2*>(ref + ((size_t)bq * 4 + z) * 2);
    const int W = c_WL[l], H = c_HL[l], st = c_ST[l];
    const float px = r2.x * (float)W + off2.x - 0.5f;
    const float py = r2.y * (float)H + off2.y - 0.5f;
    const float x0f = floorf(px), y0f = floorf(py);
    const int x0 = (int)x0f, y0 = (int)y0f;
    const float fx = px - x0f, fy = py - y0f;
    const float gx = 1.f - fx, gy = 1.f - fy;
    const bool xi0 = (x0 >= 0) && (x0 < W);
    const bool xi1 = (x0 >= -1) && (x0 < W - 1);
    const bool yi0 = (y0 >= 0) && (y0 < H);
    const bool yi1 = (y0 >= -1) && (y0 < H - 1);
    const int xc0 = min(max(x0, 0), W - 1);
    const int xc1 = min(max(x0 + 1, 0), W - 1);
    const int yc0 = min(max(y0, 0), H - 1);
    const int yc1 = min(max(y0 + 1, 0), H - 1);

    // pixel = 32 half = 64B. absolute byte offset into g_vf16.
    const uint32_t basepix = (uint32_t)(b * 8 + h) * (uint32_t)S_TOTAL;
    const uint32_t a_t0 = (basepix + (uint32_t)(st + yc0 * W + xc0)) << 6;
    const uint32_t a_b0 = (basepix + (uint32_t)(st + yc1 * W + xc0)) << 6;
    const uint32_t dx = (uint32_t)(xc1 - xc0) << 6;
    sMeta[w][lane * 2 + 0] = make_uint4(a_t0, a_b0,
        __float_as_uint(aw * gx * gy * (float)(xi0 && yi0)),
        __float_as_uint(aw * gx * fy * (float)(xi0 && yi1)));
    sMeta[w][lane * 2 + 1] = make_uint4(a_t0 + dx, a_b0 + dx,
        __float_as_uint(aw * fx * gy * (float)(xi1 && yi0)),
        __float_as_uint(aw * fx * fy * (float)(xi1 && yi1)));
    __syncwarp();

    // phase 2
    const int half = lane >> 4;          // point parity
    const int pp = (lane >> 3) & 1;      // pixel
    const int c8 = (lane & 7) * 8;       // byte offset of 4 channels (half4)
    const char* vb = reinterpret_cast<const char*>(g_vf16);
    float acc0 = 0.f, acc1 = 0.f, acc2 = 0.f, acc3 = 0.f;
#pragma unroll
    for (int it = 0; it < 16; it++) {
        const int j = 2 * it + half;
        const uint4 mt = sMeta[w][j * 2 + pp];
        const uint2 tu = *reinterpret_cast<const uint2*>(vb + mt.x + c8);
        const uint2 bu = *reinterpret_cast<const uint2*>(vb + mt.y + c8);
        const float wt = __uint_as_float(mt.z);
        const float wb = __uint_as_float(mt.w);
        const float2 t0 = __half22float2(*reinterpret_cast<const __half2*>(&tu.x));
        const float2 t1 = __half22float2(*reinterpret_cast<const __half2*>(&tu.y));
        const float2 b0 = __half22float2(*reinterpret_cast<const __half2*>(&bu.x));
        const float2 b1 = __half22float2(*reinterpret_cast<const __half2*>(&bu.y));
        acc0 = fmaf(wt, t0.x, fmaf(wb, b0.x, acc0));
        acc1 = fmaf(wt, t0.y, fmaf(wb, b0.y, acc1));
        acc2 = fmaf(wt, t1.x, fmaf(wb, b1.x, acc2));
        acc3 = fmaf(wt, t1.y, fmaf(wb, b1.y, acc3));
    }
    // reduce over pixel (xor 8) then point parity (xor 16)
#pragma unroll
    for (int o = 8; o <= 16; o <<= 1) {
        acc0 += __shfl_xor_sync(0xFFFFFFFFu, acc0, o);
        acc1 += __shfl_xor_sync(0xFFFFFFFFu, acc1, o);
        acc2 += __shfl_xor_sync(0xFFFFFFFFu, acc2, o);
        acc3 += __shfl_xor_sync(0xFFFFFFFFu, acc3, o);
    }
    if (lane < 8) {
        *reinterpret_cast<float4*>(out + (size_t)bq * 256 + h * 32 + lane * 4) =
            make_float4(acc0, acc1, acc2, acc3);
    }
}

// ---------------------------------------------------------------------------
extern "C" void kernel_launch(void* const* d_in, const int* in_sizes, int n_in,
                              void* d_out, int out_size)
{
    const float* query = (const float*)d_in[0];
    const float* value = (const float*)d_in[1];
    const float* ref   = (const float*)d_in[2];
    const float* w_off = (const float*)d_in[3];
    const float* b_off = (const float*)d_in[4];
    const float* w_att = (const float*)d_in[5];
    const float* b_att = (const float*)d_in[6];
    const float* w_val = (const float*)d_in[7];
    const float* b_val = (const float*)d_in[8];
    float* out = (float*)d_out;

    static float *p_off = nullptr, *p_attn = nullptr;
    static __nv_bfloat16 *p_vh, *p_vl, *p_qh, *p_ql, *p_wth, *p_wtl;
    if (!p_off) {
        cudaGetSymbolAddress((void**)&p_off, g_off);
        cudaGetSymbolAddress((void**)&p_attn, g_attn);
        cudaGetSymbolAddress((void**)&p_vh, g_vh);
        cudaGetSymbolAddress((void**)&p_vl, g_vl);
        cudaGetSymbolAddress((void**)&p_qh, g_qh);
        cudaGetSymbolAddress((void**)&p_ql, g_ql);
        cudaGetSymbolAddress((void**)&p_wth, g_wth);
        cudaGetSymbolAddress((void**)&p_wtl, g_wtl);
        cudaFuncSetAttribute(gemm_mma, cudaFuncAttributeMaxDynamicSharedMemorySize, 2 * STAGE_BYTES);
    }

    const int nv4 = BB * S_TOTAL * EE / 4;
    const int nq4 = BB * QQ * EE / 4;
    split_kernel<<<(nv4 + 255) / 256, 256>>>(value, p_vh, p_vl, nv4);
    split_kernel<<<(nq4 + 255) / 256, 256>>>(query, p_qh, p_ql, nq4);
    wsplit_kernel<<<(256 * 256 + 255) / 256, 256>>>(w_val, p_wth, p_wtl, 256);
    wsplit_kernel<<<(512 * 256 + 255) / 256, 256>>>(w_off, p_wth + 65536, p_wtl + 65536, 512);
    wsplit_kernel<<<(256 * 256 + 255) / 256, 256>>>(w_att, p_wth + 196608, p_wtl + 196608, 256);

    // value GEMM -> fp16 [B,NH,S,D]
    {
        dim3 grid(2, (BB * S_TOTAL + 127) / 128);
        gemm_mma<<<grid, 256, 2 * STAGE_BYTES>>>(p_vh, p_vl, p_wth, p_wtl, b_val,
                                                 nullptr, BB * S_TOTAL, 256, 1);
    }
    {
        dim3 grid(4, (BB * QQ + 127) / 128);
        gemm_mma<<<grid, 256, 2 * STAGE_BYTES>>>(p_qh, p_ql, p_wth + 65536, p_wtl + 65536,
                                                 b_off, p_off, BB * QQ, 512, 0);
    }
    {
        dim3 grid(2, (BB * QQ + 127) / 128);
        gemm_mma<<<grid, 256, 2 * STAGE_BYTES>>>(p_qh, p_ql, p_wth + 196608, p_wtl + 196608,
                                                 b_att, p_attn, BB * QQ, 256, 0);
    }
    sample_kernel<<<BB * QQ * NHH / 8, 256>>>(ref, out);
}

// round 6
// speedup vs baseline: 3.1751x; 1.1438x over previous
#include <cuda_runtime.h>
#include <cuda_fp16.h>
#include <math.h>
#include <stdint.h>

#define BB 4
#define QQ 10000
#define EE 256
#define NHH 8
#define S_TOTAL 19560

__constant__ int c_HL[4] = {92, 46, 23, 12};
__constant__ int c_WL[4] = {160, 80, 40, 20};
__constant__ int c_ST[4] = {0, 14720, 18400, 19320};

// Scratch (no cudaMalloc allowed)
__device__ __half g_vf16[BB * NHH * S_TOTAL * 32];  // value proj, [B,NH,S,D] fp16
__device__ float g_off[BB * QQ * 512];
__device__ float g_attn[BB * QQ * 256];
__device__ __half g_va[BB * S_TOTAL * EE];          // value fp16 (A operand)
__device__ __half g_qa[BB * QQ * EE];               // query fp16 (A operand)
__device__ __half g_wth[262144];                    // transposed weights hi [n][k]
__device__ __half g_wtl[262144];                    // transposed weights lo [n][k]

__device__ __forceinline__ uint32_t smem_u32(const void* p) {
    uint32_t a;
    asm("{ .reg .u64 t; cvta.to.shared.u64 t, %1; cvt.u32.u64 %0, t; }" : "=r"(a) : "l"(p));
    return a;
}

#define LDMATRIX_X4(r, addr) \
    asm volatile("ldmatrix.sync.aligned.m8n8.x4.shared.b16 {%0,%1,%2,%3}, [%4];" \
        : "=r"((r)[0]), "=r"((r)[1]), "=r"((r)[2]), "=r"((r)[3]) : "r"(addr))

#define MMA_F16(d, a, b) \
    asm volatile("mma.sync.aligned.m16n8k16.row.col.f32.f16.f16.f32 " \
        "{%0,%1,%2,%3}, {%4,%5,%6,%7}, {%8,%9}, {%0,%1,%2,%3};" \
        : "+f"((d)[0]), "+f"((d)[1]), "+f"((d)[2]), "+f"((d)[3]) \
        : "r"((a)[0]), "r"((a)[1]), "r"((a)[2]), "r"((a)[3]), "r"((b)[0]), "r"((b)[1]))

// ------------------------- convert / transpose kernels ----------------------
__global__ __launch_bounds__(256) void cvt_kernel(
    const float* __restrict__ in, __half* __restrict__ outp, int n4)
{
    int i = blockIdx.x * 256 + threadIdx.x;
    if (i >= n4) return;
    float4 v = reinterpret_cast<const float4*>(in)[i];
    __half2* ph = reinterpret_cast<__half2*>(outp);
    ph[2 * i + 0] = __floats2half2_rn(v.x, v.y);
    ph[2 * i + 1] = __floats2half2_rn(v.z, v.w);
}

__global__ __launch_bounds__(256) void wsplit_kernel(
    const float* __restrict__ w, __half* __restrict__ th,
    __half* __restrict__ tl, int N)
{
    int idx = blockIdx.x * 256 + threadIdx.x;
    if (idx >= N * 256) return;
    int n = idx >> 8, k = idx & 255;
    float v = w[k * N + n];
    __half h = __float2half_rn(v);
    th[idx] = h;
    tl[idx] = __float2half_rn(v - __half2float(h));
}

// ------------------------- mma.sync 2-term fp16 GEMM ------------------------
// C[M,N] = A @ (Bh + Bl)^T + bias. K=256. N mult of 128.
// A row-major [M][256] fp16; Bh/Bl row-major [N][256] fp16 (transposed weight).
// Block 128x128, 8 warps as 2(M) x 4(N); warp tile 64x32.
// smem: 2 stages x 3 tiles (A, Bh, Bl), each 128 rows x 48B.

#define TILE_BYTES 6144
#define STAGE_BYTES (3 * TILE_BYTES)

__device__ __forceinline__ int bdiv_s(int m) {
    return (m >= 2 * S_TOTAL) ? (m >= 3 * S_TOTAL ? 3 : 2) : (m >= S_TOTAL ? 1 : 0);
}

__device__ __forceinline__ void load_stage(
    uint32_t sbase, int stage,
    const char* A, const char* Bh, const char* Bl,
    int bm, int bn, int M, int c, int tid)
{
    const uint32_t dst0 = sbase + stage * STAGE_BYTES;
#pragma unroll
    for (int it = 0; it < 3; it++) {
        int i = tid + it * 256;
        int tile = i >> 8;
        int idx = i & 255;
        int row = idx >> 1;
        int half = (idx & 1) << 4;
        uint32_t dst = dst0 + tile * TILE_BYTES + row * 48 + half;
        const char* src;
        int ssize = 16;
        if (tile == 0) {
            src = A + (size_t)(bm + row) * 512 + c * 32 + half;
            if (bm + row >= M) ssize = 0;
        } else if (tile == 1) {
            src = Bh + (size_t)(bn + row) * 512 + c * 32 + half;
        } else {
            src = Bl + (size_t)(bn + row) * 512 + c * 32 + half;
        }
        asm volatile("cp.async.ca.shared.global [%0], [%1], 16, %2;"
                     :: "r"(dst), "l"(src), "r"(ssize) : "memory");
    }
}

// mode 0: C_f32[m][n] = acc + bias (row-major MxN)
// mode 1: value path — write fp16 to g_vf16 in [B,NH,S,D] layout
__global__ __launch_bounds__(256) void gemm_mma(
    const __half* __restrict__ A_g,
    const __half* __restrict__ Bh_g, const __half* __restrict__ Bl_g,
    const float* __restrict__ bias, float* __restrict__ C, int M, int N, int mode)
{
    extern __shared__ char smem[];
    const uint32_t sbase = smem_u32(smem);
    const int tid = threadIdx.x;
    const int wid = tid >> 5, lane = tid & 31;
    const int warp_m = wid >> 2, warp_n = wid & 3;
    const int bm = blockIdx.y * 128, bn = blockIdx.x * 128;

    const char* Ac = reinterpret_cast<const char*>(A_g);
    const char* Bhc = reinterpret_cast<const char*>(Bh_g);
    const char* Blc = reinterpret_cast<const char*>(Bl_g);

    float acc[4][4][4];
#pragma unroll
    for (int mt = 0; mt < 4; mt++)
#pragma unroll
        for (int nt = 0; nt < 4; nt++)
#pragma unroll
            for (int r = 0; r < 4; r++) acc[mt][nt][r] = 0.f;

    load_stage(sbase, 0, Ac, Bhc, Blc, bm, bn, M, 0, tid);
    asm volatile("cp.async.commit_group;" ::: "memory");
    load_stage(sbase, 1, Ac, Bhc, Blc, bm, bn, M, 1, tid);
    asm volatile("cp.async.commit_group;" ::: "memory");

    const uint32_t a_row = warp_m * 64 + (lane & 15);
    const uint32_t a_off = (uint32_t)((lane >> 4) << 4);
    const uint32_t b_row = warp_n * 32 + (lane & 7) + ((lane >> 4) << 3);
    const uint32_t b_off = (uint32_t)(((lane >> 3) & 1) << 4);

#pragma unroll 1
    for (int c = 0; c < 16; c++) {
        asm volatile("cp.async.wait_group 1;" ::: "memory");
        __syncthreads();
        const uint32_t st = sbase + (c & 1) * STAGE_BYTES;

        uint32_t ah[4][4], bh[4][2], bl[4][2];
#pragma unroll
        for (int mt = 0; mt < 4; mt++) {
            uint32_t addr = st + (a_row + mt * 16) * 48 + a_off;
            LDMATRIX_X4(ah[mt], addr);
        }
#pragma unroll
        for (int g = 0; g < 2; g++) {
            uint32_t addr = st + TILE_BYTES + (b_row + g * 16) * 48 + b_off;
            uint32_t rh[4], rl[4];
            LDMATRIX_X4(rh, addr);
            LDMATRIX_X4(rl, addr + TILE_BYTES);
            bh[2 * g][0] = rh[0]; bh[2 * g][1] = rh[1];
            bh[2 * g + 1][0] = rh[2]; bh[2 * g + 1][1] = rh[3];
            bl[2 * g][0] = rl[0]; bl[2 * g][1] = rl[1];
            bl[2 * g + 1][0] = rl[2]; bl[2 * g + 1][1] = rl[3];
        }
        __syncthreads();

        if (c + 2 < 16)
            load_stage(sbase, c & 1, Ac, Bhc, Blc, bm, bn, M, c + 2, tid);
        asm volatile("cp.async.commit_group;" ::: "memory");

#pragma unroll
        for (int mt = 0; mt < 4; mt++)
#pragma unroll
            for (int nt = 0; nt < 4; nt++) {
                MMA_F16(acc[mt][nt], ah[mt], bh[nt]);
                MMA_F16(acc[mt][nt], ah[mt], bl[nt]);
            }
    }

    const int q = lane >> 2, t = lane & 3;
    if (mode == 0) {
#pragma unroll
        for (int mt = 0; mt < 4; mt++) {
            int m0 = bm + warp_m * 64 + mt * 16 + q;
#pragma unroll
            for (int nt = 0; nt < 4; nt++) {
                int n = bn + warp_n * 32 + nt * 8 + 2 * t;
                float b0 = bias[n], b1 = bias[n + 1];
                if (m0 < M)
                    *reinterpret_cast<float2*>(C + (size_t)m0 * N + n) =
                        make_float2(acc[mt][nt][0] + b0, acc[mt][nt][1] + b1);
                if (m0 + 8 < M)
                    *reinterpret_cast<float2*>(C + (size_t)(m0 + 8) * N + n) =
                        make_float2(acc[mt][nt][2] + b0, acc[mt][nt][3] + b1);
            }
        }
    } else {
        // value path: m -> (b, s); n -> (h, d); dst = ((b*8+h)*S + s)*32 + d, fp16
        __half2* vf = reinterpret_cast<__half2*>(g_vf16);
#pragma unroll
        for (int mt = 0; mt < 4; mt++) {
            int m0 = bm + warp_m * 64 + mt * 16 + q;
#pragma unroll
            for (int nt = 0; nt < 4; nt++) {
                int n = bn + warp_n * 32 + nt * 8 + 2 * t;
                int h = n >> 5, d = n & 31;
                float b0 = bias[n], b1 = bias[n + 1];
#pragma unroll
                for (int rr = 0; rr < 2; rr++) {
                    int m = m0 + rr * 8;
                    if (m < M) {
                        int bb = bdiv_s(m);
                        int s = m - bb * S_TOTAL;
                        size_t idx = ((size_t)((bb * 8 + h)) * S_TOTAL + s) * 16 + (d >> 1);
                        vf[idx] = __floats2half2_rn(acc[mt][nt][2 * rr] + b0,
                                                    acc[mt][nt][2 * rr + 1] + b1);
                    }
                }
            }
        }
    }
}

// ------------------------- fused softmax + sampling -------------------------
__global__ __launch_bounds__(256) void sample_kernel(
    const float* __restrict__ ref, float* __restrict__ out)
{
    __shared__ uint4 sMeta[8][64];

    const int w = threadIdx.x >> 5;
    const int lane = threadIdx.x & 31;
    const int warp_global = blockIdx.x * 8 + w;
    const int h = warp_global & 7;
    const int bq = warp_global >> 3;
    const int b = bq / QQ;

    float logit = g_attn[(size_t)bq * 256 + h * 32 + lane];
    float m = logit;
#pragma unroll
    for (int o = 16; o; o >>= 1) m = fmaxf(m, __shfl_xor_sync(0xFFFFFFFFu, m, o));
    float e = __expf(logit - m);
    float s = e;
#pragma unroll
    for (int o = 16; o; o >>= 1) s += __shfl_xor_sync(0xFFFFFFFFu, s, o);
    const float aw = e / s;

    const int l = lane >> 3;
    const int p = lane & 7;
    const int z = p & 3;
    const float2 off2 = *reinterpret_cast<const float2*>(g_off + (size_t)bq * 512 + h * 64 + lane * 2);
    const float2 r2 = *reinterpret_cast<const float2*>(ref + ((size_t)bq * 4 + z) * 2);
    const int W = c_WL[l], H = c_HL[l], st = c_ST[l];
    const float px = r2.x * (float)W + off2.x - 0.5f;
    const float py = r2.y * (float)H + off2.y - 0.5f;
    const float x0f = floorf(px), y0f = floorf(py);
    const int x0 = (int)x0f, y0 = (int)y0f;
    const float fx = px - x0f, fy = py - y0f;
    const float gx = 1.f - fx, gy = 1.f - fy;
    const bool xi0 = (x0 >= 0) && (x0 < W);
    const bool xi1 = (x0 >= -1) && (x0 < W - 1);
    const bool yi0 = (y0 >= 0) && (y0 < H);
    const bool yi1 = (y0 >= -1) && (y0 < H - 1);
    const int xc0 = min(max(x0, 0), W - 1);
    const int xc1 = min(max(x0 + 1, 0), W - 1);
    const int yc0 = min(max(y0, 0), H - 1);
    const int yc1 = min(max(y0 + 1, 0), H - 1);

    const uint32_t basepix = (uint32_t)(b * 8 + h) * (uint32_t)S_TOTAL;
    const uint32_t a_t0 = (basepix + (uint32_t)(st + yc0 * W + xc0)) << 6;
    const uint32_t a_b0 = (basepix + (uint32_t)(st + yc1 * W + xc0)) << 6;
    const uint32_t dx = (uint32_t)(xc1 - xc0) << 6;
    sMeta[w][lane * 2 + 0] = make_uint4(a_t0, a_b0,
        __float_as_uint(aw * gx * gy * (float)(xi0 && yi0)),
        __float_as_uint(aw * gx * fy * (float)(xi0 && yi1)));
    sMeta[w][lane * 2 + 1] = make_uint4(a_t0 + dx, a_b0 + dx,
        __float_as_uint(aw * fx * gy * (float)(xi1 && yi0)),
        __float_as_uint(aw * fx * fy * (float)(xi1 && yi1)));
    __syncwarp();

    const int half = lane >> 4;
    const int pp = (lane >> 3) & 1;
    const int c8 = (lane & 7) * 8;
    const char* vb = reinterpret_cast<const char*>(g_vf16);
    float acc0 = 0.f, acc1 = 0.f, acc2 = 0.f, acc3 = 0.f;
#pragma unroll
    for (int it = 0; it < 16; it++) {
        const int j = 2 * it + half;
        const uint4 mt = sMeta[w][j * 2 + pp];
        const uint2 tu = *reinterpret_cast<const uint2*>(vb + mt.x + c8);
        const uint2 bu = *reinterpret_cast<const uint2*>(vb + mt.y + c8);
        const float wt = __uint_as_float(mt.z);
        const float wb = __uint_as_float(mt.w);
        const float2 t0 = __half22float2(*reinterpret_cast<const __half2*>(&tu.x));
        const float2 t1 = __half22float2(*reinterpret_cast<const __half2*>(&tu.y));
        const float2 b0 = __half22float2(*reinterpret_cast<const __half2*>(&bu.x));
        const float2 b1 = __half22float2(*reinterpret_cast<const __half2*>(&bu.y));
        acc0 = fmaf(wt, t0.x, fmaf(wb, b0.x, acc0));
        acc1 = fmaf(wt, t0.y, fmaf(wb, b0.y, acc1));
        acc2 = fmaf(wt, t1.x, fmaf(wb, b1.x, acc2));
        acc3 = fmaf(wt, t1.y, fmaf(wb, b1.y, acc3));
    }
#pragma unroll
    for (int o = 8; o <= 16; o <<= 1) {
        acc0 += __shfl_xor_sync(0xFFFFFFFFu, acc0, o);
        acc1 += __shfl_xor_sync(0xFFFFFFFFu, acc1, o);
        acc2 += __shfl_xor_sync(0xFFFFFFFFu, acc2, o);
        acc3 += __shfl_xor_sync(0xFFFFFFFFu, acc3, o);
    }
    if (lane < 8) {
        *reinterpret_cast<float4*>(out + (size_t)bq * 256 + h * 32 + lane * 4) =
            make_float4(acc0, acc1, acc2, acc3);
    }
}

// ---------------------------------------------------------------------------
extern "C" void kernel_launch(void* const* d_in, const int* in_sizes, int n_in,
                              void* d_out, int out_size)
{
    const float* query = (const float*)d_in[0];
    const float* value = (const float*)d_in[1];
    const float* ref   = (const float*)d_in[2];
    const float* w_off = (const float*)d_in[3];
    const float* b_off = (const float*)d_in[4];
    const float* w_att = (const float*)d_in[5];
    const float* b_att = (const float*)d_in[6];
    const float* w_val = (const float*)d_in[7];
    const float* b_val = (const float*)d_in[8];
    float* out = (float*)d_out;

    static float *p_off = nullptr, *p_attn = nullptr;
    static __half *p_va, *p_qa, *p_wth, *p_wtl;
    if (!p_off) {
        cudaGetSymbolAddress((void**)&p_off, g_off);
        cudaGetSymbolAddress((void**)&p_attn, g_attn);
        cudaGetSymbolAddress((void**)&p_va, g_va);
        cudaGetSymbolAddress((void**)&p_qa, g_qa);
        cudaGetSymbolAddress((void**)&p_wth, g_wth);
        cudaGetSymbolAddress((void**)&p_wtl, g_wtl);
        cudaFuncSetAttribute(gemm_mma, cudaFuncAttributeMaxDynamicSharedMemorySize, 2 * STAGE_BYTES);
    }

    const int nv4 = BB * S_TOTAL * EE / 4;
    const int nq4 = BB * QQ * EE / 4;
    cvt_kernel<<<(nv4 + 255) / 256, 256>>>(value, p_va, nv4);
    cvt_kernel<<<(nq4 + 255) / 256, 256>>>(query, p_qa, nq4);
    wsplit_kernel<<<(256 * 256 + 255) / 256, 256>>>(w_val, p_wth, p_wtl, 256);
    wsplit_kernel<<<(512 * 256 + 255) / 256, 256>>>(w_off, p_wth + 65536, p_wtl + 65536, 512);
    wsplit_kernel<<<(256 * 256 + 255) / 256, 256>>>(w_att, p_wth + 196608, p_wtl + 196608, 256);

    // value GEMM -> fp16 [B,NH,S,D]
    {
        dim3 grid(2, (BB * S_TOTAL + 127) / 128);
        gemm_mma<<<grid, 256, 2 * STAGE_BYTES>>>(p_va, p_wth, p_wtl, b_val,
                                                 nullptr, BB * S_TOTAL, 256, 1);
    }
    {
        dim3 grid(4, (BB * QQ + 127) / 128);
        gemm_mma<<<grid, 256, 2 * STAGE_BYTES>>>(p_qa, p_wth + 65536, p_wtl + 65536,
                                                 b_off, p_off, BB * QQ, 512, 0);
    }
    {
        dim3 grid(2, (BB * QQ + 127) / 128);
        gemm_mma<<<grid, 256, 2 * STAGE_BYTES>>>(p_qa, p_wth + 196608, p_wtl + 196608,
                                                 b_att, p_attn, BB * QQ, 256, 0);
    }
    sample_kernel<<<BB * QQ * NHH / 8, 256>>>(ref, out);
}

// round 7
// speedup vs baseline: 3.2016x; 1.0084x over previous
#include <cuda_runtime.h>
#include <cuda_fp16.h>
#include <math.h>
#include <stdint.h>

#define BB 4
#define QQ 10000
#define EE 256
#define NHH 8
#define S_TOTAL 19560

__constant__ int c_HL[4] = {92, 46, 23, 12};
__constant__ int c_WL[4] = {160, 80, 40, 20};
__constant__ int c_ST[4] = {0, 14720, 18400, 19320};

// Scratch (no cudaMalloc allowed)
__device__ __half g_vf16[BB * NHH * S_TOTAL * 32];  // value proj, [B,NH,S,D] fp16
__device__ float g_off[BB * QQ * 512];
__device__ float g_attn[BB * QQ * 256];
__device__ __half g_va[BB * S_TOTAL * EE];          // value fp16 (A operand)
__device__ __half g_qa[BB * QQ * EE];               // query fp16 (A operand)
__device__ __half g_wth[262144];                    // transposed weights hi [n][k]
__device__ __half g_wtl[262144];                    // transposed weights lo [n][k]

__device__ __forceinline__ uint32_t smem_u32(const void* p) {
    uint32_t a;
    asm("{ .reg .u64 t; cvta.to.shared.u64 t, %1; cvt.u32.u64 %0, t; }" : "=r"(a) : "l"(p));
    return a;
}

#define LDMATRIX_X4(r, addr) \
    asm volatile("ldmatrix.sync.aligned.m8n8.x4.shared.b16 {%0,%1,%2,%3}, [%4];" \
        : "=r"((r)[0]), "=r"((r)[1]), "=r"((r)[2]), "=r"((r)[3]) : "r"(addr))

#define MMA_F16(d, a, b) \
    asm volatile("mma.sync.aligned.m16n8k16.row.col.f32.f16.f16.f32 " \
        "{%0,%1,%2,%3}, {%4,%5,%6,%7}, {%8,%9}, {%0,%1,%2,%3};" \
        : "+f"((d)[0]), "+f"((d)[1]), "+f"((d)[2]), "+f"((d)[3]) \
        : "r"((a)[0]), "r"((a)[1]), "r"((a)[2]), "r"((a)[3]), "r"((b)[0]), "r"((b)[1]))

// ------------------------- convert / transpose kernels ----------------------
__global__ __launch_bounds__(256) void cvt_kernel(
    const float* __restrict__ in, __half* __restrict__ outp, int n4)
{
    int i = blockIdx.x * 256 + threadIdx.x;
    if (i >= n4) return;
    float4 v = reinterpret_cast<const float4*>(in)[i];
    __half2* ph = reinterpret_cast<__half2*>(outp);
    ph[2 * i + 0] = __floats2half2_rn(v.x, v.y);
    ph[2 * i + 1] = __floats2half2_rn(v.z, v.w);
}

__global__ __launch_bounds__(256) void wsplit_kernel(
    const float* __restrict__ w, __half* __restrict__ th,
    __half* __restrict__ tl, int N)
{
    int idx = blockIdx.x * 256 + threadIdx.x;
    if (idx >= N * 256) return;
    int n = idx >> 8, k = idx & 255;
    float v = w[k * N + n];
    __half h = __float2half_rn(v);
    th[idx] = h;
    tl[idx] = __float2half_rn(v - __half2float(h));
}

// ------------------------- mma.sync 2-term fp16 GEMM ------------------------
// C[M,N] = A @ (Bh + Bl)^T + bias. K=256. N mult of 128.
// Block 128x128, 8 warps as 2(M) x 4(N); warp tile 64x32.
// smem: 3 stages x 3 tiles (A, Bh, Bl), each 128 rows x 48B; single sync/chunk.

#define TILE_BYTES 6144
#define STAGE_BYTES (3 * TILE_BYTES)

__device__ __forceinline__ int bdiv_s(int m) {
    return (m >= 2 * S_TOTAL) ? (m >= 3 * S_TOTAL ? 3 : 2) : (m >= S_TOTAL ? 1 : 0);
}

__device__ __forceinline__ void load_stage(
    uint32_t sbase, int stage,
    const char* A, const char* Bh, const char* Bl,
    int bm, int bn, int M, int c, int tid)
{
    const uint32_t dst0 = sbase + stage * STAGE_BYTES;
#pragma unroll
    for (int it = 0; it < 3; it++) {
        int i = tid + it * 256;
        int tile = i >> 8;
        int idx = i & 255;
        int row = idx >> 1;
        int half = (idx & 1) << 4;
        uint32_t dst = dst0 + tile * TILE_BYTES + row * 48 + half;
        const char* src;
        int ssize = 16;
        if (tile == 0) {
            src = A + (size_t)(bm + row) * 512 + c * 32 + half;
            if (bm + row >= M) ssize = 0;
        } else if (tile == 1) {
            src = Bh + (size_t)(bn + row) * 512 + c * 32 + half;
        } else {
            src = Bl + (size_t)(bn + row) * 512 + c * 32 + half;
        }
        asm volatile("cp.async.ca.shared.global [%0], [%1], 16, %2;"
                     :: "r"(dst), "l"(src), "r"(ssize) : "memory");
    }
}

// mode 0: C_f32[m][n] = acc + bias (row-major MxN)
// mode 1: value path — write fp16 to g_vf16 in [B,NH,S,D] layout
__global__ __launch_bounds__(256) void gemm_mma(
    const __half* __restrict__ A_g,
    const __half* __restrict__ Bh_g, const __half* __restrict__ Bl_g,
    const float* __restrict__ bias, float* __restrict__ C, int M, int N, int mode)
{
    extern __shared__ char smem[];
    const uint32_t sbase = smem_u32(smem);
    const int tid = threadIdx.x;
    const int wid = tid >> 5, lane = tid & 31;
    const int warp_m = wid >> 2, warp_n = wid & 3;
    const int bm = blockIdx.y * 128, bn = blockIdx.x * 128;

    const char* Ac = reinterpret_cast<const char*>(A_g);
    const char* Bhc = reinterpret_cast<const char*>(Bh_g);
    const char* Blc = reinterpret_cast<const char*>(Bl_g);

    float acc[4][4][4];
#pragma unroll
    for (int mt = 0; mt < 4; mt++)
#pragma unroll
        for (int nt = 0; nt < 4; nt++)
#pragma unroll
            for (int r = 0; r < 4; r++) acc[mt][nt][r] = 0.f;

    load_stage(sbase, 0, Ac, Bhc, Blc, bm, bn, M, 0, tid);
    asm volatile("cp.async.commit_group;" ::: "memory");
    load_stage(sbase, 1, Ac, Bhc, Blc, bm, bn, M, 1, tid);
    asm volatile("cp.async.commit_group;" ::: "memory");

    const uint32_t a_row = warp_m * 64 + (lane & 15);
    const uint32_t a_off = (uint32_t)((lane >> 4) << 4);
    const uint32_t b_row = warp_n * 32 + (lane & 7) + ((lane >> 4) << 3);
    const uint32_t b_off = (uint32_t)(((lane >> 3) & 1) << 4);

    int rd_stage = 0, wr_stage = 2;
#pragma unroll 1
    for (int c = 0; c < 16; c++) {
        asm volatile("cp.async.wait_group 1;" ::: "memory");
        __syncthreads();
        const uint32_t st = sbase + rd_stage * STAGE_BYTES;

        uint32_t ah[4][4], bh[4][2], bl[4][2];
#pragma unroll
        for (int mt = 0; mt < 4; mt++) {
            uint32_t addr = st + (a_row + mt * 16) * 48 + a_off;
            LDMATRIX_X4(ah[mt], addr);
        }
#pragma unroll
        for (int g = 0; g < 2; g++) {
            uint32_t addr = st + TILE_BYTES + (b_row + g * 16) * 48 + b_off;
            uint32_t rh[4], rl[4];
            LDMATRIX_X4(rh, addr);
            LDMATRIX_X4(rl, addr + TILE_BYTES);
            bh[2 * g][0] = rh[0]; bh[2 * g][1] = rh[1];
            bh[2 * g + 1][0] = rh[2]; bh[2 * g + 1][1] = rh[3];
            bl[2 * g][0] = rl[0]; bl[2 * g][1] = rl[1];
            bl[2 * g + 1][0] = rl[2]; bl[2 * g + 1][1] = rl[3];
        }

        // issue next-next chunk into the buffer whose reads finished last chunk
        if (c + 2 < 16)
            load_stage(sbase, wr_stage, Ac, Bhc, Blc, bm, bn, M, c + 2, tid);
        asm volatile("cp.async.commit_group;" ::: "memory");

#pragma unroll
        for (int mt = 0; mt < 4; mt++)
#pragma unroll
            for (int nt = 0; nt < 4; nt++) {
                MMA_F16(acc[mt][nt], ah[mt], bh[nt]);
                MMA_F16(acc[mt][nt], ah[mt], bl[nt]);
            }

        rd_stage = (rd_stage == 2) ? 0 : rd_stage + 1;
        wr_stage = (wr_stage == 2) ? 0 : wr_stage + 1;
    }

    const int q = lane >> 2, t = lane & 3;
    if (mode == 0) {
#pragma unroll
        for (int mt = 0; mt < 4; mt++) {
            int m0 = bm + warp_m * 64 + mt * 16 + q;
#pragma unroll
            for (int nt = 0; nt < 4; nt++) {
                int n = bn + warp_n * 32 + nt * 8 + 2 * t;
                float b0 = bias[n], b1 = bias[n + 1];
                if (m0 < M)
                    *reinterpret_cast<float2*>(C + (size_t)m0 * N + n) =
                        make_float2(acc[mt][nt][0] + b0, acc[mt][nt][1] + b1);
                if (m0 + 8 < M)
                    *reinterpret_cast<float2*>(C + (size_t)(m0 + 8) * N + n) =
                        make_float2(acc[mt][nt][2] + b0, acc[mt][nt][3] + b1);
            }
        }
    } else {
        __half2* vf = reinterpret_cast<__half2*>(g_vf16);
#pragma unroll
        for (int mt = 0; mt < 4; mt++) {
            int m0 = bm + warp_m * 64 + mt * 16 + q;
#pragma unroll
            for (int nt = 0; nt < 4; nt++) {
                int n = bn + warp_n * 32 + nt * 8 + 2 * t;
                int h = n >> 5, d = n & 31;
                float b0 = bias[n], b1 = bias[n + 1];
#pragma unroll
                for (int rr = 0; rr < 2; rr++) {
                    int m = m0 + rr * 8;
                    if (m < M) {
                        int bb = bdiv_s(m);
                        int s = m - bb * S_TOTAL;
                        size_t idx = ((size_t)((bb * 8 + h)) * S_TOTAL + s) * 16 + (d >> 1);
                        vf[idx] = __floats2half2_rn(acc[mt][nt][2 * rr] + b0,
                                                    acc[mt][nt][2 * rr + 1] + b1);
                    }
                }
            }
        }
    }
}

// ------------------------- fused softmax + sampling -------------------------
__global__ __launch_bounds__(256) void sample_kernel(
    const float* __restrict__ ref, float* __restrict__ out)
{
    __shared__ uint4 sMeta[8][64];

    const int w = threadIdx.x >> 5;
    const int lane = threadIdx.x & 31;
    const int warp_global = blockIdx.x * 8 + w;
    const int h = warp_global & 7;
    const int bq = warp_global >> 3;
    const int b = bq / QQ;

    float logit = g_attn[(size_t)bq * 256 + h * 32 + lane];
    float m = logit;
#pragma unroll
    for (int o = 16; o; o >>= 1) m = fmaxf(m, __shfl_xor_sync(0xFFFFFFFFu, m, o));
    float e = __expf(logit - m);
    float s = e;
#pragma unroll
    for (int o = 16; o; o >>= 1) s += __shfl_xor_sync(0xFFFFFFFFu, s, o);
    const float aw = e / s;

    const int l = lane >> 3;
    const int p = lane & 7;
    const int z = p & 3;
    const float2 off2 = *reinterpret_cast<const float2*>(g_off + (size_t)bq * 512 + h * 64 + lane * 2);
    const float2 r2 = *reinterpret_cast<const float2*>(ref + ((size_t)bq * 4 + z) * 2);
    const int W = c_WL[l], H = c_HL[l], st = c_ST[l];
    const float px = r2.x * (float)W + off2.x - 0.5f;
    const float py = r2.y * (float)H + off2.y - 0.5f;
    const float x0f = floorf(px), y0f = floorf(py);
    const int x0 = (int)x0f, y0 = (int)y0f;
    const float fx = px - x0f, fy = py - y0f;
    const float gx = 1.f - fx, gy = 1.f - fy;
    const bool xi0 = (x0 >= 0) && (x0 < W);
    const bool xi1 = (x0 >= -1) && (x0 < W - 1);
    const bool yi0 = (y0 >= 0) && (y0 < H);
    const bool yi1 = (y0 >= -1) && (y0 < H - 1);
    const int xc0 = min(max(x0, 0), W - 1);
    const int xc1 = min(max(x0 + 1, 0), W - 1);
    const int yc0 = min(max(y0, 0), H - 1);
    const int yc1 = min(max(y0 + 1, 0), H - 1);

    const uint32_t basepix = (uint32_t)(b * 8 + h) * (uint32_t)S_TOTAL;
    const uint32_t a_t0 = (basepix + (uint32_t)(st + yc0 * W + xc0)) << 6;
    const uint32_t a_b0 = (basepix + (uint32_t)(st + yc1 * W + xc0)) << 6;
    const uint32_t dx = (uint32_t)(xc1 - xc0) << 6;
    sMeta[w][lane * 2 + 0] = make_uint4(a_t0, a_b0,
        __float_as_uint(aw * gx * gy * (float)(xi0 && yi0)),
        __float_as_uint(aw * gx * fy * (float)(xi0 && yi1)));
    sMeta[w][lane * 2 + 1] = make_uint4(a_t0 + dx, a_b0 + dx,
        __float_as_uint(aw * fx * gy * (float)(xi1 && yi0)),
        __float_as_uint(aw * fx * fy * (float)(xi1 && yi1)));
    __syncwarp();

    const int half = lane >> 4;
    const int pp = (lane >> 3) & 1;
    const int c8 = (lane & 7) * 8;
    const char* vb = reinterpret_cast<const char*>(g_vf16);
    float acc0 = 0.f, acc1 = 0.f, acc2 = 0.f, acc3 = 0.f;
#pragma unroll
    for (int it = 0; it < 16; it++) {
        const int j = 2 * it + half;
        const uint4 mt = sMeta[w][j * 2 + pp];
        const uint2 tu = *reinterpret_cast<const uint2*>(vb + mt.x + c8);
        const uint2 bu = *reinterpret_cast<const uint2*>(vb + mt.y + c8);
        const float wt = __uint_as_float(mt.z);
        const float wb = __uint_as_float(mt.w);
        const float2 t0 = __half22float2(*reinterpret_cast<const __half2*>(&tu.x));
        const float2 t1 = __half22float2(*reinterpret_cast<const __half2*>(&tu.y));
        const float2 b0 = __half22float2(*reinterpret_cast<const __half2*>(&bu.x));
        const float2 b1 = __half22float2(*reinterpret_cast<const __half2*>(&bu.y));
        acc0 = fmaf(wt, t0.x, fmaf(wb, b0.x, acc0));
        acc1 = fmaf(wt, t0.y, fmaf(wb, b0.y, acc1));
        acc2 = fmaf(wt, t1.x, fmaf(wb, b1.x, acc2));
        acc3 = fmaf(wt, t1.y, fmaf(wb, b1.y, acc3));
    }
#pragma unroll
    for (int o = 8; o <= 16; o <<= 1) {
        acc0 += __shfl_xor_sync(0xFFFFFFFFu, acc0, o);
        acc1 += __shfl_xor_sync(0xFFFFFFFFu, acc1, o);
        acc2 += __shfl_xor_sync(0xFFFFFFFFu, acc2, o);
        acc3 += __shfl_xor_sync(0xFFFFFFFFu, acc3, o);
    }
    if (lane < 8) {
        *reinterpret_cast<float4*>(out + (size_t)bq * 256 + h * 32 + lane * 4) =
            make_float4(acc0, acc1, acc2, acc3);
    }
}

// ---------------------------------------------------------------------------
extern "C" void kernel_launch(void* const* d_in, const int* in_sizes, int n_in,
                              void* d_out, int out_size)
{
    const float* query = (const float*)d_in[0];
    const float* value = (const float*)d_in[1];
    const float* ref   = (const float*)d_in[2];
    const float* w_off = (const float*)d_in[3];
    const float* b_off = (const float*)d_in[4];
    const float* w_att = (const float*)d_in[5];
    const float* b_att = (const float*)d_in[6];
    const float* w_val = (const float*)d_in[7];
    const float* b_val = (const float*)d_in[8];
    float* out = (float*)d_out;

    static float *p_off = nullptr, *p_attn = nullptr;
    static __half *p_va, *p_qa, *p_wth, *p_wtl;
    if (!p_off) {
        cudaGetSymbolAddress((void**)&p_off, g_off);
        cudaGetSymbolAddress((void**)&p_attn, g_attn);
        cudaGetSymbolAddress((void**)&p_va, g_va);
        cudaGetSymbolAddress((void**)&p_qa, g_qa);
        cudaGetSymbolAddress((void**)&p_wth, g_wth);
        cudaGetSymbolAddress((void**)&p_wtl, g_wtl);
        cudaFuncSetAttribute(gemm_mma, cudaFuncAttributeMaxDynamicSharedMemorySize, 3 * STAGE_BYTES);
    }

    const int nv4 = BB * S_TOTAL * EE / 4;
    const int nq4 = BB * QQ * EE / 4;
    cvt_kernel<<<(nv4 + 255) / 256, 256>>>(value, p_va, nv4);
    cvt_kernel<<<(nq4 + 255) / 256, 256>>>(query, p_qa, nq4);
    wsplit_kernel<<<(256 * 256 + 255) / 256, 256>>>(w_val, p_wth, p_wtl, 256);
    wsplit_kernel<<<(512 * 256 + 255) / 256, 256>>>(w_off, p_wth + 65536, p_wtl + 65536, 512);
    wsplit_kernel<<<(256 * 256 + 255) / 256, 256>>>(w_att, p_wth + 196608, p_wtl + 196608, 256);

    // value GEMM -> fp16 [B,NH,S,D]
    {
        dim3 grid(2, (BB * S_TOTAL + 127) / 128);
        gemm_mma<<<grid, 256, 3 * STAGE_BYTES>>>(p_va, p_wth, p_wtl, b_val,
                                                 nullptr, BB * S_TOTAL, 256, 1);
    }
    {
        dim3 grid(4, (BB * QQ + 127) / 128);
        gemm_mma<<<grid, 256, 3 * STAGE_BYTES>>>(p_qa, p_wth + 65536, p_wtl + 65536,
                                                 b_off, p_off, BB * QQ, 512, 0);
    }
    {
        dim3 grid(2, (BB * QQ + 127) / 128);
        gemm_mma<<<grid, 256, 3 * STAGE_BYTES>>>(p_qa, p_wth + 196608, p_wtl + 196608,
                                                 b_att, p_attn, BB * QQ, 256, 0);
    }
    sample_kernel<<<BB * QQ * NHH / 8, 256>>>(ref, out);
}

// round 8
// speedup vs baseline: 3.6835x; 1.1505x over previous
#include <cuda_runtime.h>
#include <cuda_fp16.h>
#include <math.h>
#include <stdint.h>

#define BB 4
#define QQ 10000
#define EE 256
#define NHH 8
#define S_TOTAL 19560

__constant__ int c_HL[4] = {92, 46, 23, 12};
__constant__ int c_WL[4] = {160, 80, 40, 20};
__constant__ int c_ST[4] = {0, 14720, 18400, 19320};

// Scratch (no cudaMalloc allowed)
__device__ __half g_vf16[BB * NHH * S_TOTAL * 32];  // value proj, [B,NH,S,D] fp16
__device__ float g_off[BB * QQ * 512];
__device__ float g_attn[BB * QQ * 256];
__device__ __half g_va[BB * S_TOTAL * EE];          // value fp16 (A operand)
__device__ __half g_qa[BB * QQ * EE];               // query fp16 (A operand)
__device__ __half g_wth[262144];                    // transposed weights fp16 [n][k]

__device__ __forceinline__ uint32_t smem_u32(const void* p) {
    uint32_t a;
    asm("{ .reg .u64 t; cvta.to.shared.u64 t, %1; cvt.u32.u64 %0, t; }" : "=r"(a) : "l"(p));
    return a;
}

#define LDMATRIX_X4(r, addr) \
    asm volatile("ldmatrix.sync.aligned.m8n8.x4.shared.b16 {%0,%1,%2,%3}, [%4];" \
        : "=r"((r)[0]), "=r"((r)[1]), "=r"((r)[2]), "=r"((r)[3]) : "r"(addr))

#define MMA_F16(d, a, b) \
    asm volatile("mma.sync.aligned.m16n8k16.row.col.f32.f16.f16.f32 " \
        "{%0,%1,%2,%3}, {%4,%5,%6,%7}, {%8,%9}, {%0,%1,%2,%3};" \
        : "+f"((d)[0]), "+f"((d)[1]), "+f"((d)[2]), "+f"((d)[3]) \
        : "r"((a)[0]), "r"((a)[1]), "r"((a)[2]), "r"((a)[3]), "r"((b)[0]), "r"((b)[1]))

// ------------------------- convert / transpose kernels ----------------------
__global__ __launch_bounds__(256) void cvt_kernel(
    const float* __restrict__ in, __half* __restrict__ outp, int n4)
{
    int i = blockIdx.x * 256 + threadIdx.x;
    if (i >= n4) return;
    float4 v = reinterpret_cast<const float4*>(in)[i];
    __half2* ph = reinterpret_cast<__half2*>(outp);
    ph[2 * i + 0] = __floats2half2_rn(v.x, v.y);
    ph[2 * i + 1] = __floats2half2_rn(v.z, v.w);
}

__global__ __launch_bounds__(256) void wcvt_kernel(
    const float* __restrict__ w, __half* __restrict__ th, int N)
{
    int idx = blockIdx.x * 256 + threadIdx.x;
    if (idx >= N * 256) return;
    int n = idx >> 8, k = idx & 255;
    th[idx] = __float2half_rn(w[k * N + n]);
}

// ------------------------- mma.sync fp16 GEMM -------------------------------
// C[M,N] = A @ B^T + bias. K=256. N mult of 128.
// Block 128x128, 8 warps as 2(M) x 4(N); warp tile 64x32.
// smem: 3 stages x 2 tiles (A, B), each 128 rows x 48B; single sync per chunk.

#define TILE_BYTES 6144
#define STAGE_BYTES (2 * TILE_BYTES)

__device__ __forceinline__ int bdiv_s(int m) {
    return (m >= 2 * S_TOTAL) ? (m >= 3 * S_TOTAL ? 3 : 2) : (m >= S_TOTAL ? 1 : 0);
}

__device__ __forceinline__ void load_stage(
    uint32_t sbase, int stage,
    const char* A, const char* Bm,
    int bm, int bn, int M, int c, int tid)
{
    const uint32_t dst0 = sbase + stage * STAGE_BYTES;
#pragma unroll
    for (int it = 0; it < 2; it++) {
        int i = tid + it * 256;
        int tile = i >> 8;
        int idx = i & 255;
        int row = idx >> 1;
        int half = (idx & 1) << 4;
        uint32_t dst = dst0 + tile * TILE_BYTES + row * 48 + half;
        const char* src;
        int ssize = 16;
        if (tile == 0) {
            src = A + (size_t)(bm + row) * 512 + c * 32 + half;
            if (bm + row >= M) ssize = 0;
        } else {
            src = Bm + (size_t)(bn + row) * 512 + c * 32 + half;
        }
        asm volatile("cp.async.ca.shared.global [%0], [%1], 16, %2;"
                     :: "r"(dst), "l"(src), "r"(ssize) : "memory");
    }
}

// mode 0: C_f32[m][n] = acc + bias (row-major MxN)
// mode 1: value path — write fp16 to g_vf16 in [B,NH,S,D] layout
__global__ __launch_bounds__(256) void gemm_mma(
    const __half* __restrict__ A_g, const __half* __restrict__ B_g,
    const float* __restrict__ bias, float* __restrict__ C, int M, int N, int mode)
{
    extern __shared__ char smem[];
    const uint32_t sbase = smem_u32(smem);
    const int tid = threadIdx.x;
    const int wid = tid >> 5, lane = tid & 31;
    const int warp_m = wid >> 2, warp_n = wid & 3;
    const int bm = blockIdx.y * 128, bn = blockIdx.x * 128;

    const char* Ac = reinterpret_cast<const char*>(A_g);
    const char* Bc = reinterpret_cast<const char*>(B_g);

    float acc[4][4][4];
#pragma unroll
    for (int mt = 0; mt < 4; mt++)
#pragma unroll
        for (int nt = 0; nt < 4; nt++)
#pragma unroll
            for (int r = 0; r < 4; r++) acc[mt][nt][r] = 0.f;

    load_stage(sbase, 0, Ac, Bc, bm, bn, M, 0, tid);
    asm volatile("cp.async.commit_group;" ::: "memory");
    load_stage(sbase, 1, Ac, Bc, bm, bn, M, 1, tid);
    asm volatile("cp.async.commit_group;" ::: "memory");

    const uint32_t a_row = warp_m * 64 + (lane & 15);
    const uint32_t a_off = (uint32_t)((lane >> 4) << 4);
    const uint32_t b_row = warp_n * 32 + (lane & 7) + ((lane >> 4) << 3);
    const uint32_t b_off = (uint32_t)(((lane >> 3) & 1) << 4);

    int rd_stage = 0, wr_stage = 2;
#pragma unroll 1
    for (int c = 0; c < 16; c++) {
        asm volatile("cp.async.wait_group 1;" ::: "memory");
        __syncthreads();
        const uint32_t st = sbase + rd_stage * STAGE_BYTES;

        uint32_t ah[4][4], bh[4][2];
#pragma unroll
        for (int mt = 0; mt < 4; mt++) {
            uint32_t addr = st + (a_row + mt * 16) * 48 + a_off;
            LDMATRIX_X4(ah[mt], addr);
        }
#pragma unroll
        for (int g = 0; g < 2; g++) {
            uint32_t addr = st + TILE_BYTES + (b_row + g * 16) * 48 + b_off;
            uint32_t rh[4];
            LDMATRIX_X4(rh, addr);
            bh[2 * g][0] = rh[0]; bh[2 * g][1] = rh[1];
            bh[2 * g + 1][0] = rh[2]; bh[2 * g + 1][1] = rh[3];
        }

        if (c + 2 < 16)
            load_stage(sbase, wr_stage, Ac, Bc, bm, bn, M, c + 2, tid);
        asm volatile("cp.async.commit_group;" ::: "memory");

#pragma unroll
        for (int mt = 0; mt < 4; mt++)
#pragma unroll
            for (int nt = 0; nt < 4; nt++)
                MMA_F16(acc[mt][nt], ah[mt], bh[nt]);

        rd_stage = (rd_stage == 2) ? 0 : rd_stage + 1;
        wr_stage = (wr_stage == 2) ? 0 : wr_stage + 1;
    }

    const int q = lane >> 2, t = lane & 3;
    if (mode == 0) {
#pragma unroll
        for (int mt = 0; mt < 4; mt++) {
            int m0 = bm + warp_m * 64 + mt * 16 + q;
#pragma unroll
            for (int nt = 0; nt < 4; nt++) {
                int n = bn + warp_n * 32 + nt * 8 + 2 * t;
                float b0 = bias[n], b1 = bias[n + 1];
                if (m0 < M)
                    *reinterpret_cast<float2*>(C + (size_t)m0 * N + n) =
                        make_float2(acc[mt][nt][0] + b0, acc[mt][nt][1] + b1);
                if (m0 + 8 < M)
                    *reinterpret_cast<float2*>(C + (size_t)(m0 + 8) * N + n) =
                        make_float2(acc[mt][nt][2] + b0, acc[mt][nt][3] + b1);
            }
        }
    } else {
        __half2* vf = reinterpret_cast<__half2*>(g_vf16);
#pragma unroll
        for (int mt = 0; mt < 4; mt++) {
            int m0 = bm + warp_m * 64 + mt * 16 + q;
#pragma unroll
            for (int nt = 0; nt < 4; nt++) {
                int n = bn + warp_n * 32 + nt * 8 + 2 * t;
                int h = n >> 5, d = n & 31;
                float b0 = bias[n], b1 = bias[n + 1];
#pragma unroll
                for (int rr = 0; rr < 2; rr++) {
                    int m = m0 + rr * 8;
                    if (m < M) {
                        int bb = bdiv_s(m);
                        int s = m - bb * S_TOTAL;
                        size_t idx = ((size_t)((bb * 8 + h)) * S_TOTAL + s) * 16 + (d >> 1);
                        vf[idx] = __floats2half2_rn(acc[mt][nt][2 * rr] + b0,
                                                    acc[mt][nt][2 * rr + 1] + b1);
                    }
                }
            }
        }
    }
}

// ------------------------- fused softmax + sampling -------------------------
__global__ __launch_bounds__(256) void sample_kernel(
    const float* __restrict__ ref, float* __restrict__ out)
{
    __shared__ uint4 sMeta[8][64];

    const int w = threadIdx.x >> 5;
    const int lane = threadIdx.x & 31;
    const int warp_global = blockIdx.x * 8 + w;
    const int h = warp_global & 7;
    const int bq = warp_global >> 3;
    const int b = bq / QQ;

    float logit = g_attn[(size_t)bq * 256 + h * 32 + lane];
    float m = logit;
#pragma unroll
    for (int o = 16; o; o >>= 1) m = fmaxf(m, __shfl_xor_sync(0xFFFFFFFFu, m, o));
    float e = __expf(logit - m);
    float s = e;
#pragma unroll
    for (int o = 16; o; o >>= 1) s += __shfl_xor_sync(0xFFFFFFFFu, s, o);
    const float aw = e / s;

    const int l = lane >> 3;
    const int p = lane & 7;
    const int z = p & 3;
    const float2 off2 = *reinterpret_cast<const float2*>(g_off + (size_t)bq * 512 + h * 64 + lane * 2);
    const float2 r2 = *reinterpret_cast<const float2*>(ref + ((size_t)bq * 4 + z) * 2);
    const int W = c_WL[l], H = c_HL[l], st = c_ST[l];
    const float px = r2.x * (float)W + off2.x - 0.5f;
    const float py = r2.y * (float)H + off2.y - 0.5f;
    const float x0f = floorf(px), y0f = floorf(py);
    const int x0 = (int)x0f, y0 = (int)y0f;
    const float fx = px - x0f, fy = py - y0f;
    const float gx = 1.f - fx, gy = 1.f - fy;
    const bool xi0 = (x0 >= 0) && (x0 < W);
    const bool xi1 = (x0 >= -1) && (x0 < W - 1);
    const bool yi0 = (y0 >= 0) && (y0 < H);
    const bool yi1 = (y0 >= -1) && (y0 < H - 1);
    const int xc0 = min(max(x0, 0), W - 1);
    const int xc1 = min(max(x0 + 1, 0), W - 1);
    const int yc0 = min(max(y0, 0), H - 1);
    const int yc1 = min(max(y0 + 1, 0), H - 1);

    const uint32_t basepix = (uint32_t)(b * 8 + h) * (uint32_t)S_TOTAL;
    const uint32_t a_t0 = (basepix + (uint32_t)(st + yc0 * W + xc0)) << 6;
    const uint32_t a_b0 = (basepix + (uint32_t)(st + yc1 * W + xc0)) << 6;
    const uint32_t dx = (uint32_t)(xc1 - xc0) << 6;
    sMeta[w][lane * 2 + 0] = make_uint4(a_t0, a_b0,
        __float_as_uint(aw * gx * gy * (float)(xi0 && yi0)),
        __float_as_uint(aw * gx * fy * (float)(xi0 && yi1)));
    sMeta[w][lane * 2 + 1] = make_uint4(a_t0 + dx, a_b0 + dx,
        __float_as_uint(aw * fx * gy * (float)(xi1 && yi0)),
        __float_as_uint(aw * fx * fy * (float)(xi1 && yi1)));
    __syncwarp();

    const int half = lane >> 4;
    const int pp = (lane >> 3) & 1;
    const int c8 = (lane & 7) * 8;
    const char* vb = reinterpret_cast<const char*>(g_vf16);
    float acc0 = 0.f, acc1 = 0.f, acc2 = 0.f, acc3 = 0.f;
#pragma unroll
    for (int it = 0; it < 16; it++) {
        const int j = 2 * it + half;
        const uint4 mt = sMeta[w][j * 2 + pp];
        const uint2 tu = *reinterpret_cast<const uint2*>(vb + mt.x + c8);
        const uint2 bu = *reinterpret_cast<const uint2*>(vb + mt.y + c8);
        const float wt = __uint_as_float(mt.z);
        const float wb = __uint_as_float(mt.w);
        const float2 t0 = __half22float2(*reinterpret_cast<const __half2*>(&tu.x));
        const float2 t1 = __half22float2(*reinterpret_cast<const __half2*>(&tu.y));
        const float2 b0 = __half22float2(*reinterpret_cast<const __half2*>(&bu.x));
        const float2 b1 = __half22float2(*reinterpret_cast<const __half2*>(&bu.y));
        acc0 = fmaf(wt, t0.x, fmaf(wb, b0.x, acc0));
        acc1 = fmaf(wt, t0.y, fmaf(wb, b0.y, acc1));
        acc2 = fmaf(wt, t1.x, fmaf(wb, b1.x, acc2));
        acc3 = fmaf(wt, t1.y, fmaf(wb, b1.y, acc3));
    }
#pragma unroll
    for (int o = 8; o <= 16; o <<= 1) {
        acc0 += __shfl_xor_sync(0xFFFFFFFFu, acc0, o);
        acc1 += __shfl_xor_sync(0xFFFFFFFFu, acc1, o);
        acc2 += __shfl_xor_sync(0xFFFFFFFFu, acc2, o);
        acc3 += __shfl_xor_sync(0xFFFFFFFFu, acc3, o);
    }
    if (lane < 8) {
        *reinterpret_cast<float4*>(out + (size_t)bq * 256 + h * 32 + lane * 4) =
            make_float4(acc0, acc1, acc2, acc3);
    }
}

// ---------------------------------------------------------------------------
extern "C" void kernel_launch(void* const* d_in, const int* in_sizes, int n_in,
                              void* d_out, int out_size)
{
    const float* query = (const float*)d_in[0];
    const float* value = (const float*)d_in[1];
    const float* ref   = (const float*)d_in[2];
    const float* w_off = (const float*)d_in[3];
    const float* b_off = (const float*)d_in[4];
    const float* w_att = (const float*)d_in[5];
    const float* b_att = (const float*)d_in[6];
    const float* w_val = (const float*)d_in[7];
    const float* b_val = (const float*)d_in[8];
    float* out = (float*)d_out;

    static float *p_off = nullptr, *p_attn = nullptr;
    static __half *p_va, *p_qa, *p_wth;
    if (!p_off) {
        cudaGetSymbolAddress((void**)&p_off, g_off);
        cudaGetSymbolAddress((void**)&p_attn, g_attn);
        cudaGetSymbolAddress((void**)&p_va, g_va);
        cudaGetSymbolAddress((void**)&p_qa, g_qa);
        cudaGetSymbolAddress((void**)&p_wth, g_wth);
        cudaFuncSetAttribute(gemm_mma, cudaFuncAttributeMaxDynamicSharedMemorySize, 3 * STAGE_BYTES);
    }

    const int nv4 = BB * S_TOTAL * EE / 4;
    const int nq4 = BB * QQ * EE / 4;
    cvt_kernel<<<(nv4 + 255) / 256, 256>>>(value, p_va, nv4);
    cvt_kernel<<<(nq4 + 255) / 256, 256>>>(query, p_qa, nq4);
    wcvt_kernel<<<(256 * 256 + 255) / 256, 256>>>(w_val, p_wth, 256);
    wcvt_kernel<<<(512 * 256 + 255) / 256, 256>>>(w_off, p_wth + 65536, 512);
    wcvt_kernel<<<(256 * 256 + 255) / 256, 256>>>(w_att, p_wth + 196608, 256);

    // value GEMM -> fp16 [B,NH,S,D]
    {
        dim3 grid(2, (BB * S_TOTAL + 127) / 128);
        gemm_mma<<<grid, 256, 3 * STAGE_BYTES>>>(p_va, p_wth, b_val,
                                                 nullptr, BB * S_TOTAL, 256, 1);
    }
    {
        dim3 grid(4, (BB * QQ + 127) / 128);
        gemm_mma<<<grid, 256, 3 * STAGE_BYTES>>>(p_qa, p_wth + 65536,
                                                 b_off, p_off, BB * QQ, 512, 0);
    }
    {
        dim3 grid(2, (BB * QQ + 127) / 128);
        gemm_mma<<<grid, 256, 3 * STAGE_BYTES>>>(p_qa, p_wth + 196608,
                                                 b_att, p_attn, BB * QQ, 256, 0);
    }
    sample_kernel<<<BB * QQ * NHH / 8, 256>>>(ref, out);
}

// round 9
// speedup vs baseline: 3.8535x; 1.0462x over previous
#include <cuda_runtime.h>
#include <cuda_fp16.h>
#include <math.h>
#include <stdint.h>

#define BB 4
#define QQ 10000
#define EE 256
#define NHH 8
#define S_TOTAL 19560

__constant__ int c_HL[4] = {92, 46, 23, 12};
__constant__ int c_WL[4] = {160, 80, 40, 20};
__constant__ int c_ST[4] = {0, 14720, 18400, 19320};

// Scratch (no cudaMalloc allowed)
__device__ __half g_vf16[BB * NHH * S_TOTAL * 32];  // value proj, [B,NH,S,D] fp16
__device__ float g_oa[BB * QQ * 768];               // [off(512) | attn(256)] per (b,q)
__device__ __half g_va[BB * S_TOTAL * EE];          // value fp16 (A operand)
__device__ __half g_qa[BB * QQ * EE];               // query fp16 (A operand)
__device__ __half g_wth[262144];                    // weights fp16 [n][k]: val(256) | off+attn(768)

__device__ __forceinline__ uint32_t smem_u32(const void* p) {
    uint32_t a;
    asm("{ .reg .u64 t; cvta.to.shared.u64 t, %1; cvt.u32.u64 %0, t; }" : "=r"(a) : "l"(p));
    return a;
}

#define LDMATRIX_X4(r, addr) \
    asm volatile("ldmatrix.sync.aligned.m8n8.x4.shared.b16 {%0,%1,%2,%3}, [%4];" \
        : "=r"((r)[0]), "=r"((r)[1]), "=r"((r)[2]), "=r"((r)[3]) : "r"(addr))

#define MMA_F16(d, a, b) \
    asm volatile("mma.sync.aligned.m16n8k16.row.col.f32.f16.f16.f32 " \
        "{%0,%1,%2,%3}, {%4,%5,%6,%7}, {%8,%9}, {%0,%1,%2,%3};" \
        : "+f"((d)[0]), "+f"((d)[1]), "+f"((d)[2]), "+f"((d)[3]) \
        : "r"((a)[0]), "r"((a)[1]), "r"((a)[2]), "r"((a)[3]), "r"((b)[0]), "r"((b)[1]))

// ------------------------- prep kernels -------------------------------------
__global__ __launch_bounds__(256) void cvt_kernel(
    const float* __restrict__ in, __half* __restrict__ outp, int n4)
{
    int i = blockIdx.x * 256 + threadIdx.x;
    if (i >= n4) return;
    float4 v = reinterpret_cast<const float4*>(in)[i];
    __half2* ph = reinterpret_cast<__half2*>(outp);
    ph[2 * i + 0] = __floats2half2_rn(v.x, v.y);
    ph[2 * i + 1] = __floats2half2_rn(v.z, v.w);
}

// transpose+convert all three weights into g_wth:
//   [0,65536): w_val  (n<256)
//   [65536,262144): w_off (n<512) then w_att (n in 512..767)
__global__ __launch_bounds__(256) void wprep_kernel(
    const float* __restrict__ w_val, const float* __restrict__ w_off,
    const float* __restrict__ w_att, __half* __restrict__ th)
{
    int idx = blockIdx.x * 256 + threadIdx.x;
    float v;
    if (idx < 65536) {
        int n = idx >> 8, k = idx & 255;
        v = w_val[k * 256 + n];
    } else {
        int j = idx - 65536;
        int n = j >> 8, k = j & 255;
        v = (n < 512) ? w_off[k * 512 + n] : w_att[k * 256 + (n - 512)];
    }
    th[idx] = __float2half_rn(v);
}

// ------------------------- mma.sync fp16 GEMM, K-chunk 32 -------------------
// C[M,N] = A @ B^T + bias. K=256 (8 chunks of 32). N mult of 128.
// Block 128x128, 8 warps as 2(M) x 4(N); warp tile 64x32.
// smem: 3 stages x 2 tiles (A,B), tile = 128 rows x 80B (64B payload + pad).

#define TILE_BYTES 10240
#define STAGE_BYTES (2 * TILE_BYTES)

__device__ __forceinline__ int bdiv_s(int m) {
    return (m >= 2 * S_TOTAL) ? (m >= 3 * S_TOTAL ? 3 : 2) : (m >= S_TOTAL ? 1 : 0);
}

__device__ __forceinline__ void load_stage(
    uint32_t sbase, int stage, const char* A, const char* Bm,
    int bm, int bn, int M, int c, int tid)
{
    const uint32_t dst0 = sbase + stage * STAGE_BYTES;
#pragma unroll
    for (int it = 0; it < 4; it++) {
        int i = tid + it * 256;
        int tile = i >> 9;
        int idx = i & 511;
        int row = idx >> 2;
        int g = (idx & 3) << 4;
        uint32_t dst = dst0 + tile * TILE_BYTES + row * 80 + g;
        const char* src;
        int ssize = 16;
        if (tile == 0) {
            src = A + (size_t)(bm + row) * 512 + c * 64 + g;
            if (bm + row >= M) ssize = 0;
        } else {
            src = Bm + (size_t)(bn + row) * 512 + c * 64 + g;
        }
        asm volatile("cp.async.ca.shared.global [%0], [%1], 16, %2;"
                     :: "r"(dst), "l"(src), "r"(ssize) : "memory");
    }
}

// mode 0: C[m][n] = acc + bias (bias1 for n<bsplit, bias2 for n>=bsplit)
// mode 1: value path — write fp16 to g_vf16 in [B,NH,S,D] layout (bias1)
__global__ __launch_bounds__(256) void gemm_mma(
    const __half* __restrict__ A_g, const __half* __restrict__ B_g,
    const float* __restrict__ bias1, const float* __restrict__ bias2, int bsplit,
    float* __restrict__ C, int M, int N, int mode)
{
    extern __shared__ char smem[];
    const uint32_t sbase = smem_u32(smem);
    const int tid = threadIdx.x;
    const int wid = tid >> 5, lane = tid & 31;
    const int warp_m = wid >> 2, warp_n = wid & 3;
    const int bm = blockIdx.y * 128, bn = blockIdx.x * 128;

    const char* Ac = reinterpret_cast<const char*>(A_g);
    const char* Bc = reinterpret_cast<const char*>(B_g);

    float acc[4][4][4];
#pragma unroll
    for (int mt = 0; mt < 4; mt++)
#pragma unroll
        for (int nt = 0; nt < 4; nt++)
#pragma unroll
            for (int r = 0; r < 4; r++) acc[mt][nt][r] = 0.f;

    load_stage(sbase, 0, Ac, Bc, bm, bn, M, 0, tid);
    asm volatile("cp.async.commit_group;" ::: "memory");
    load_stage(sbase, 1, Ac, Bc, bm, bn, M, 1, tid);
    asm volatile("cp.async.commit_group;" ::: "memory");

    const uint32_t a_row = warp_m * 64 + (lane & 15);
    const uint32_t a_off = (uint32_t)((lane >> 4) << 4);
    const uint32_t b_row = warp_n * 32 + (lane & 7) + ((lane >> 4) << 3);
    const uint32_t b_off = (uint32_t)(((lane >> 3) & 1) << 4);

    int rd_stage = 0, wr_stage = 2;
#pragma unroll 1
    for (int c = 0; c < 8; c++) {
        asm volatile("cp.async.wait_group 1;" ::: "memory");
        __syncthreads();
        const uint32_t st = sbase + rd_stage * STAGE_BYTES;

        uint32_t ah[4][4], bh[4][2];
        // ---- K-group 0 ----
#pragma unroll
        for (int mt = 0; mt < 4; mt++)
            LDMATRIX_X4(ah[mt], st + (a_row + mt * 16) * 80 + a_off);
#pragma unroll
        for (int g = 0; g < 2; g++) {
            uint32_t rh[4];
            LDMATRIX_X4(rh, st + TILE_BYTES + (b_row + g * 16) * 80 + b_off);
            bh[2 * g][0] = rh[0]; bh[2 * g][1] = rh[1];
            bh[2 * g + 1][0] = rh[2]; bh[2 * g + 1][1] = rh[3];
        }

        if (c + 2 < 8)
            load_stage(sbase, wr_stage, Ac, Bc, bm, bn, M, c + 2, tid);
        asm volatile("cp.async.commit_group;" ::: "memory");

#pragma unroll
        for (int mt = 0; mt < 4; mt++)
#pragma unroll
            for (int nt = 0; nt < 4; nt++)
                MMA_F16(acc[mt][nt], ah[mt], bh[nt]);

        // ---- K-group 1 (bytes +32 within the 64B row payload) ----
#pragma unroll
        for (int mt = 0; mt < 4; mt++)
            LDMATRIX_X4(ah[mt], st + (a_row + mt * 16) * 80 + 32 + a_off);
#pragma unroll
        for (int g = 0; g < 2; g++) {
            uint32_t rh[4];
            LDMATRIX_X4(rh, st + TILE_BYTES + (b_row + g * 16) * 80 + 32 + b_off);
            bh[2 * g][0] = rh[0]; bh[2 * g][1] = rh[1];
            bh[2 * g + 1][0] = rh[2]; bh[2 * g + 1][1] = rh[3];
        }
#pragma unroll
        for (int mt = 0; mt < 4; mt++)
#pragma unroll
            for (int nt = 0; nt < 4; nt++)
                MMA_F16(acc[mt][nt], ah[mt], bh[nt]);

        rd_stage = (rd_stage == 2) ? 0 : rd_stage + 1;
        wr_stage = (wr_stage == 2) ? 0 : wr_stage + 1;
    }

    const int q = lane >> 2, t = lane & 3;
    if (mode == 0) {
#pragma unroll
        for (int mt = 0; mt < 4; mt++) {
            int m0 = bm + warp_m * 64 + mt * 16 + q;
#pragma unroll
            for (int nt = 0; nt < 4; nt++) {
                int n = bn + warp_n * 32 + nt * 8 + 2 * t;
                float b0 = (n < bsplit) ? bias1[n] : bias2[n - bsplit];
                float b1 = (n + 1 < bsplit) ? bias1[n + 1] : bias2[n + 1 - bsplit];
                if (m0 < M)
                    *reinterpret_cast<float2*>(C + (size_t)m0 * N + n) =
                        make_float2(acc[mt][nt][0] + b0, acc[mt][nt][1] + b1);
                if (m0 + 8 < M)
                    *reinterpret_cast<float2*>(C + (size_t)(m0 + 8) * N + n) =
                        make_float2(acc[mt][nt][2] + b0, acc[mt][nt][3] + b1);
            }
        }
    } else {
        __half2* vf = reinterpret_cast<__half2*>(g_vf16);
#pragma unroll
        for (int mt = 0; mt < 4; mt++) {
            int m0 = bm + warp_m * 64 + mt * 16 + q;
#pragma unroll
            for (int nt = 0; nt < 4; nt++) {
                int n = bn + warp_n * 32 + nt * 8 + 2 * t;
                int h = n >> 5, d = n & 31;
                float b0 = bias1[n], b1 = bias1[n + 1];
#pragma unroll
                for (int rr = 0; rr < 2; rr++) {
                    int m = m0 + rr * 8;
                    if (m < M) {
                        int bb = bdiv_s(m);
                        int s = m - bb * S_TOTAL;
                        size_t idx = ((size_t)((bb * 8 + h)) * S_TOTAL + s) * 16 + (d >> 1);
                        vf[idx] = __floats2half2_rn(acc[mt][nt][2 * rr] + b0,
                                                    acc[mt][nt][2 * rr + 1] + b1);
                    }
                }
            }
        }
    }
}

// ------------------------- fused softmax + sampling -------------------------
// Phase 1: lane = point; per pixel p in {x0,x1}: {addr_top, addr_bot, w_top, w_bot}.
// Phase 2: lane = [half(1)|row(1)|pixel(1)|chunk(2)]; one LDS.128 + one LDG.128
//          per iteration (16 iters cover 32 points); 8 channels per lane.
__global__ __launch_bounds__(256) void sample_kernel(
    const float* __restrict__ ref, float* __restrict__ out)
{
    __shared__ uint4 sMeta[8][64];

    const int w = threadIdx.x >> 5;
    const int lane = threadIdx.x & 31;
    const int warp_global = blockIdx.x * 8 + w;
    const int h = warp_global & 7;
    const int bq = warp_global >> 3;
    const int b = bq / QQ;

    float logit = g_oa[(size_t)bq * 768 + 512 + h * 32 + lane];
    float m = logit;
#pragma unroll
    for (int o = 16; o; o >>= 1) m = fmaxf(m, __shfl_xor_sync(0xFFFFFFFFu, m, o));
    float e = __expf(logit - m);
    float s = e;
#pragma unroll
    for (int o = 16; o; o >>= 1) s += __shfl_xor_sync(0xFFFFFFFFu, s, o);
    const float aw = e / s;

    const int l = lane >> 3;
    const int p = lane & 7;
    const int z = p & 3;
    const float2 off2 = *reinterpret_cast<const float2*>(g_oa + (size_t)bq * 768 + h * 64 + lane * 2);
    const float2 r2 = *reinterpret_cast<const float2*>(ref + ((size_t)bq * 4 + z) * 2);
    const int W = c_WL[l], H = c_HL[l], st = c_ST[l];
    const float px = r2.x * (float)W + off2.x - 0.5f;
    const float py = r2.y * (float)H + off2.y - 0.5f;
    const float x0f = floorf(px), y0f = floorf(py);
    const int x0 = (int)x0f, y0 = (int)y0f;
    const float fx = px - x0f, fy = py - y0f;
    const float gx = 1.f - fx, gy = 1.f - fy;
    const bool xi0 = (x0 >= 0) && (x0 < W);
    const bool xi1 = (x0 >= -1) && (x0 < W - 1);
    const bool yi0 = (y0 >= 0) && (y0 < H);
    const bool yi1 = (y0 >= -1) && (y0 < H - 1);
    const int xc0 = min(max(x0, 0), W - 1);
    const int xc1 = min(max(x0 + 1, 0), W - 1);
    const int yc0 = min(max(y0, 0), H - 1);
    const int yc1 = min(max(y0 + 1, 0), H - 1);

    const uint32_t basepix = (uint32_t)(b * 8 + h) * (uint32_t)S_TOTAL;
    const uint32_t a_t0 = (basepix + (uint32_t)(st + yc0 * W + xc0)) << 6;
    const uint32_t a_b0 = (basepix + (uint32_t)(st + yc1 * W + xc0)) << 6;
    const uint32_t dx = (uint32_t)(xc1 - xc0) << 6;
    sMeta[w][lane * 2 + 0] = make_uint4(a_t0, a_b0,
        __float_as_uint(aw * gx * gy * (float)(xi0 && yi0)),
        __float_as_uint(aw * gx * fy * (float)(xi0 && yi1)));
    sMeta[w][lane * 2 + 1] = make_uint4(a_t0 + dx, a_b0 + dx,
        __float_as_uint(aw * fx * gy * (float)(xi1 && yi0)),
        __float_as_uint(aw * fx * fy * (float)(xi1 && yi1)));
    __syncwarp();

    const int half = lane >> 4;          // point parity
    const int row = (lane >> 3) & 1;     // top/bottom
    const int pixel = (lane >> 2) & 1;   // x0/x1
    const int chunk = (lane & 3) * 16;   // 16B of the 64B pixel
    const char* vb = reinterpret_cast<const char*>(g_vf16);
    float a0 = 0.f, a1 = 0.f, a2 = 0.f, a3 = 0.f, a4 = 0.f, a5 = 0.f, a6 = 0.f, a7 = 0.f;
#pragma unroll
    for (int it = 0; it < 16; it++) {
        const int j = 2 * it + half;
        const uint4 mt = sMeta[w][j * 2 + pixel];
        const uint32_t addr = (row ? mt.y : mt.x) + chunk;
        const float wgt = __uint_as_float(row ? mt.w : mt.z);
        const uint4 v = *reinterpret_cast<const uint4*>(vb + addr);
        const float2 f0 = __half22float2(*reinterpret_cast<const __half2*>(&v.x));
        const float2 f1 = __half22float2(*reinterpret_cast<const __half2*>(&v.y));
        const float2 f2 = __half22float2(*reinterpret_cast<const __half2*>(&v.z));
        const float2 f3 = __half22float2(*reinterpret_cast<const __half2*>(&v.w));
        a0 = fmaf(wgt, f0.x, a0); a1 = fmaf(wgt, f0.y, a1);
        a2 = fmaf(wgt, f1.x, a2); a3 = fmaf(wgt, f1.y, a3);
        a4 = fmaf(wgt, f2.x, a4); a5 = fmaf(wgt, f2.y, a5);
        a6 = fmaf(wgt, f3.x, a6); a7 = fmaf(wgt, f3.y, a7);
    }
    // reduce over pixel (xor4), row (xor8), point parity (xor16)
#pragma unroll
    for (int o = 4; o <= 16; o <<= 1) {
        a0 += __shfl_xor_sync(0xFFFFFFFFu, a0, o);
        a1 += __shfl_xor_sync(0xFFFFFFFFu, a1, o);
        a2 += __shfl_xor_sync(0xFFFFFFFFu, a2, o);
        a3 += __shfl_xor_sync(0xFFFFFFFFu, a3, o);
        a4 += __shfl_xor_sync(0xFFFFFFFFu, a4, o);
        a5 += __shfl_xor_sync(0xFFFFFFFFu, a5, o);
        a6 += __shfl_xor_sync(0xFFFFFFFFu, a6, o);
        a7 += __shfl_xor_sync(0xFFFFFFFFu, a7, o);
    }
    if (lane < 4) {
        float* op = out + (size_t)bq * 256 + h * 32 + lane * 8;
        *reinterpret_cast<float4*>(op) = make_float4(a0, a1, a2, a3);
        *reinterpret_cast<float4*>(op + 4) = make_float4(a4, a5, a6, a7);
    }
}

// ---------------------------------------------------------------------------
extern "C" void kernel_launch(void* const* d_in, const int* in_sizes, int n_in,
                              void* d_out, int out_size)
{
    const float* query = (const float*)d_in[0];
    const float* value = (const float*)d_in[1];
    const float* ref   = (const float*)d_in[2];
    const float* w_off = (const float*)d_in[3];
    const float* b_off = (const float*)d_in[4];
    const float* w_att = (const float*)d_in[5];
    const float* b_att = (const float*)d_in[6];
    const float* w_val = (const float*)d_in[7];
    const float* b_val = (const float*)d_in[8];
    float* out = (float*)d_out;

    static float* p_oa = nullptr;
    static __half *p_va, *p_qa, *p_wth;
    if (!p_oa) {
        cudaGetSymbolAddress((void**)&p_oa, g_oa);
        cudaGetSymbolAddress((void**)&p_va, g_va);
        cudaGetSymbolAddress((void**)&p_qa, g_qa);
        cudaGetSymbolAddress((void**)&p_wth, g_wth);
        cudaFuncSetAttribute(gemm_mma, cudaFuncAttributeMaxDynamicSharedMemorySize, 3 * STAGE_BYTES);
    }

    const int nv4 = BB * S_TOTAL * EE / 4;
    const int nq4 = BB * QQ * EE / 4;
    cvt_kernel<<<(nv4 + 255) / 256, 256>>>(value, p_va, nv4);
    cvt_kernel<<<(nq4 + 255) / 256, 256>>>(query, p_qa, nq4);
    wprep_kernel<<<262144 / 256, 256>>>(w_val, w_off, w_att, p_wth);

    // value GEMM -> fp16 [B,NH,S,D]
    {
        dim3 grid(2, (BB * S_TOTAL + 127) / 128);
        gemm_mma<<<grid, 256, 3 * STAGE_BYTES>>>(p_va, p_wth, b_val, b_val, 1 << 30,
                                                 nullptr, BB * S_TOTAL, 256, 1);
    }
    // merged off+attn GEMM: N=768 into g_oa
    {
        dim3 grid(6, (BB * QQ + 127) / 128);
        gemm_mma<<<grid, 256, 3 * STAGE_BYTES>>>(p_qa, p_wth + 65536, b_off, b_att, 512,
                                                 p_oa, BB * QQ, 768, 0);
    }
    sample_kernel<<<BB * QQ * NHH / 8, 256>>>(ref, out);
}